// round 1
// baseline (speedup 1.0000x reference)
#include <cuda_runtime.h>
#include <math_constants.h>

// Problem constants (fixed by the dataset)
#define BQ    256      // number of queries
#define NKEYS 200000   // number of stored keys
#define DIM   128      // key/query dim
#define SLOT  256      // slot dim
#define TOPK  8

// GEMM tiling
#define BM  128
#define BN  128
#define PAD 132        // smem row stride (floats): 4*PAD mod 32 banks -> 2-way worst case on transpose store

// Scratch: full score matrix [BQ, NKEYS] (204.8 MB). __device__ global (no cudaMalloc).
__device__ float g_scores[(size_t)BQ * NKEYS];

// ---------------------------------------------------------------------------
// Kernel 1: scores[b][n] = sum_d Q[b][d] * K[n][d]
// 128x128 tile per block, full D=128 depth in one smem stage, 8x8 per thread.
// ---------------------------------------------------------------------------
__global__ __launch_bounds__(256) void gemm_scores(const float* __restrict__ Q,
                                                   const float* __restrict__ K) {
    extern __shared__ float smem[];
    float* Qs = smem;                 // [DIM][PAD] transposed: Qs[d][m]
    float* Ks = smem + DIM * PAD;     // [DIM][PAD] transposed: Ks[d][n]

    const int tid    = threadIdx.x;
    const int n_base = blockIdx.x * BN;
    const int m_base = blockIdx.y * BM;

    // Load mapping: lane m-part = tid&7 (rows), d4 = tid>>3 (float4 along D).
    // gmem: 8 rows x 64B per warp -> fully-used 32B sectors.
    const int mloc = tid & 7;
    const int d4   = tid >> 3;

    #pragma unroll
    for (int it = 0; it < 16; ++it) {
        int m = mloc + it * 8;
        float4 v = *(const float4*)(Q + (size_t)(m_base + m) * DIM + d4 * 4);
        Qs[(d4 * 4 + 0) * PAD + m] = v.x;
        Qs[(d4 * 4 + 1) * PAD + m] = v.y;
        Qs[(d4 * 4 + 2) * PAD + m] = v.z;
        Qs[(d4 * 4 + 3) * PAD + m] = v.w;
    }
    #pragma unroll
    for (int it = 0; it < 16; ++it) {
        int n  = mloc + it * 8;
        int gn = n_base + n;
        float4 v = make_float4(0.f, 0.f, 0.f, 0.f);
        if (gn < NKEYS)
            v = *(const float4*)(K + (size_t)gn * DIM + d4 * 4);
        Ks[(d4 * 4 + 0) * PAD + n] = v.x;
        Ks[(d4 * 4 + 1) * PAD + n] = v.y;
        Ks[(d4 * 4 + 2) * PAD + n] = v.z;
        Ks[(d4 * 4 + 3) * PAD + n] = v.w;
    }
    __syncthreads();

    const int tx = tid & 15;
    const int ty = tid >> 4;
    const int m0 = ty * 8;
    const int n0 = tx * 8;

    float acc[8][8];
    #pragma unroll
    for (int i = 0; i < 8; ++i)
        #pragma unroll
        for (int j = 0; j < 8; ++j)
            acc[i][j] = 0.f;

    #pragma unroll 8
    for (int k = 0; k < DIM; ++k) {
        float a[8], b[8];
        *(float4*)&a[0] = *(const float4*)&Qs[k * PAD + m0];
        *(float4*)&a[4] = *(const float4*)&Qs[k * PAD + m0 + 4];
        *(float4*)&b[0] = *(const float4*)&Ks[k * PAD + n0];
        *(float4*)&b[4] = *(const float4*)&Ks[k * PAD + n0 + 4];
        #pragma unroll
        for (int i = 0; i < 8; ++i)
            #pragma unroll
            for (int j = 0; j < 8; ++j)
                acc[i][j] = fmaf(a[i], b[j], acc[i][j]);
    }

    // Store 8x8 per thread (float4, NKEYS % 4 == 0 so gn%4==0 vectors are all-in or all-out)
    #pragma unroll
    for (int i = 0; i < 8; ++i) {
        size_t rowoff = (size_t)(m_base + m0 + i) * NKEYS;
        #pragma unroll
        for (int j = 0; j < 8; j += 4) {
            int gn = n_base + n0 + j;
            if (gn < NKEYS)
                *(float4*)(g_scores + rowoff + gn) =
                    make_float4(acc[i][j], acc[i][j+1], acc[i][j+2], acc[i][j+3]);
        }
    }
}

// ---------------------------------------------------------------------------
// Kernel 2: per-query top-8 over the score row + slot gather.
// One block per query, 512 threads. Register-resident sorted top-8 per thread
// (guarded unrolled bubble -> rare), then 8-round argmax merge in smem.
// ---------------------------------------------------------------------------
#define TK_THREADS 512

__global__ __launch_bounds__(TK_THREADS) void topk_gather(const float* __restrict__ slots,
                                                          float* __restrict__ out_slots,
                                                          float* __restrict__ out_scores) {
    const int b   = blockIdx.x;
    const int tid = threadIdx.x;
    const float* row = g_scores + (size_t)b * NKEYS;

    float ts[TOPK];
    int   ti[TOPK];
    #pragma unroll
    for (int j = 0; j < TOPK; ++j) { ts[j] = -CUDART_INF_F; ti[j] = 0; }

    for (int n = tid; n < NKEYS; n += TK_THREADS) {
        float s = __ldg(row + n);
        if (s > ts[TOPK - 1]) {
            float cs = s; int ci = n;
            #pragma unroll
            for (int j = 0; j < TOPK; ++j) {
                if (cs > ts[j]) {
                    float tf = ts[j]; ts[j] = cs; cs = tf;
                    int   t2 = ti[j]; ti[j] = ci; ci = t2;
                }
            }
        }
    }

    __shared__ float ss[TK_THREADS * TOPK];
    __shared__ int   si[TK_THREADS * TOPK];
    #pragma unroll
    for (int j = 0; j < TOPK; ++j) {
        ss[tid * TOPK + j] = ts[j];
        si[tid * TOPK + j] = ti[j];
    }
    __syncthreads();

    __shared__ float rs[TK_THREADS];
    __shared__ int   rp[TK_THREADS];
    __shared__ float wscore[TOPK];
    __shared__ int   widx[TOPK];

    for (int r = 0; r < TOPK; ++r) {
        float best = -CUDART_INF_F;
        int   bpos = 0;
        #pragma unroll
        for (int j = 0; j < TOPK; ++j) {
            int p = tid + j * TK_THREADS;
            float v = ss[p];
            if (v > best) { best = v; bpos = p; }
        }
        rs[tid] = best;
        rp[tid] = bpos;
        __syncthreads();
        for (int st = TK_THREADS / 2; st > 0; st >>= 1) {
            if (tid < st) {
                if (rs[tid + st] > rs[tid]) {
                    rs[tid] = rs[tid + st];
                    rp[tid] = rp[tid + st];
                }
            }
            __syncthreads();
        }
        if (tid == 0) {
            int p = rp[0];
            wscore[r] = ss[p];
            widx[r]   = si[p];
            ss[p] = -CUDART_INF_F;   // remove winner
        }
        __syncthreads();
    }

    if (tid < TOPK)
        out_scores[b * TOPK + tid] = wscore[tid];

    // Gather 8 slot rows of 256 floats each
    for (int e = tid; e < TOPK * SLOT; e += TK_THREADS) {
        int j = e >> 8;        // which neighbor (SLOT == 256)
        int i = e & (SLOT - 1);
        out_slots[((size_t)b * TOPK + j) * SLOT + i] = slots[(size_t)widx[j] * SLOT + i];
    }
}

// ---------------------------------------------------------------------------
extern "C" void kernel_launch(void* const* d_in, const int* in_sizes, int n_in,
                              void* d_out, int out_size) {
    const float* Q = (const float*)d_in[0];   // [256, 128]
    const float* K = (const float*)d_in[1];   // [200000, 128]
    const float* S = (const float*)d_in[2];   // [200000, 256]
    // d_in[3] is k == 8, fixed.

    float* out        = (float*)d_out;
    float* out_slots  = out;                                  // [256, 8, 256]
    float* out_scores = out + (size_t)BQ * TOPK * SLOT;       // [256, 8]

    size_t smem_bytes = 2ull * DIM * PAD * sizeof(float);     // 135168 B
    cudaFuncSetAttribute(gemm_scores, cudaFuncAttributeMaxDynamicSharedMemorySize,
                         (int)smem_bytes);

    dim3 grid((NKEYS + BN - 1) / BN, BQ / BM);
    gemm_scores<<<grid, 256, smem_bytes>>>(Q, K);
    topk_gather<<<BQ, TK_THREADS>>>(S, out_slots, out_scores);
}

// round 2
// speedup vs baseline: 1.0610x; 1.0610x over previous
#include <cuda_runtime.h>
#include <math_constants.h>

#define BQ    256
#define NKEYS 200000
#define DIM   128
#define SLOT  256
#define TOPK  8

#define BM  128
#define BN  128
#define PAD 132

#define NCHUNK 8
#define CHUNK  (NKEYS / NCHUNK)   // 25000

__device__ float g_scores[(size_t)BQ * NKEYS];
__device__ float g_cand_s[BQ * NCHUNK * TOPK];
__device__ int   g_cand_i[BQ * NCHUNK * TOPK];

typedef unsigned long long u64;

__device__ __forceinline__ u64 pack2(float lo, float hi) {
    u64 r;
    asm("mov.b64 %0, {%1, %2};" : "=l"(r) : "f"(lo), "f"(hi));
    return r;
}
__device__ __forceinline__ void fma2(u64& d, u64 a, u64 b) {
    asm("fma.rn.f32x2 %0, %1, %2, %3;" : "=l"(d) : "l"(a), "l"(b), "l"(d));
}

// ---------------------------------------------------------------------------
// Kernel 1: scores = Q @ K^T via packed f32x2 FMA (2 FMAs/op, rt=2)
// 128x128 tile, 8x8 per thread (accumulated as 8x4 f32x2 pairs along n)
// ---------------------------------------------------------------------------
__global__ __launch_bounds__(256) void gemm_scores(const float* __restrict__ Q,
                                                   const float* __restrict__ K) {
    extern __shared__ float smem[];
    float* Qs = smem;                 // [DIM][PAD], Qs[d][m]
    float* Ks = smem + DIM * PAD;     // [DIM][PAD], Ks[d][n]

    const int tid    = threadIdx.x;
    const int n_base = blockIdx.x * BN;
    const int m_base = blockIdx.y * BM;

    const int mloc = tid & 7;
    const int d4   = tid >> 3;

    #pragma unroll
    for (int it = 0; it < 16; ++it) {
        int m = mloc + it * 8;
        float4 v = *(const float4*)(Q + (size_t)(m_base + m) * DIM + d4 * 4);
        Qs[(d4 * 4 + 0) * PAD + m] = v.x;
        Qs[(d4 * 4 + 1) * PAD + m] = v.y;
        Qs[(d4 * 4 + 2) * PAD + m] = v.z;
        Qs[(d4 * 4 + 3) * PAD + m] = v.w;
    }
    #pragma unroll
    for (int it = 0; it < 16; ++it) {
        int n  = mloc + it * 8;
        int gn = n_base + n;
        float4 v = make_float4(0.f, 0.f, 0.f, 0.f);
        if (gn < NKEYS)
            v = *(const float4*)(K + (size_t)gn * DIM + d4 * 4);
        Ks[(d4 * 4 + 0) * PAD + n] = v.x;
        Ks[(d4 * 4 + 1) * PAD + n] = v.y;
        Ks[(d4 * 4 + 2) * PAD + n] = v.z;
        Ks[(d4 * 4 + 3) * PAD + n] = v.w;
    }
    __syncthreads();

    const int tx = tid & 15;
    const int ty = tid >> 4;
    const int m0 = ty * 8;
    const int n0 = tx * 8;

    u64 acc2[8][4];
    #pragma unroll
    for (int i = 0; i < 8; ++i)
        #pragma unroll
        for (int j = 0; j < 4; ++j)
            acc2[i][j] = pack2(0.f, 0.f);

    #pragma unroll 8
    for (int k = 0; k < DIM; ++k) {
        float a[8];
        *(float4*)&a[0] = *(const float4*)&Qs[k * PAD + m0];
        *(float4*)&a[4] = *(const float4*)&Qs[k * PAD + m0 + 4];
        // b pairs: adjacent n values, 16B-aligned in smem (PAD*4 = 528 = 33*16)
        ulonglong2 p0 = *(const ulonglong2*)&Ks[k * PAD + n0];
        ulonglong2 p1 = *(const ulonglong2*)&Ks[k * PAD + n0 + 4];
        u64 b2[4] = { p0.x, p0.y, p1.x, p1.y };
        #pragma unroll
        for (int i = 0; i < 8; ++i) {
            u64 aa = pack2(a[i], a[i]);
            #pragma unroll
            for (int j = 0; j < 4; ++j)
                fma2(acc2[i][j], aa, b2[j]);
        }
    }

    // Store 8x8 per thread; packed layout matches float order (little-endian)
    #pragma unroll
    for (int i = 0; i < 8; ++i) {
        size_t rowoff = (size_t)(m_base + m0 + i) * NKEYS;
        #pragma unroll
        for (int j = 0; j < 2; ++j) {
            int gn = n_base + n0 + j * 4;
            if (gn < NKEYS)
                *(ulonglong2*)(g_scores + rowoff + gn) =
                    make_ulonglong2(acc2[i][j * 2], acc2[i][j * 2 + 1]);
        }
    }
}

// ---------------------------------------------------------------------------
// Kernel 2a: per-(query, chunk) partial top-8. grid (NCHUNK, BQ), 256 threads.
// ---------------------------------------------------------------------------
#define SCAN_T 256

__global__ __launch_bounds__(SCAN_T) void topk_scan() {
    const int c   = blockIdx.x;
    const int b   = blockIdx.y;
    const int tid = threadIdx.x;

    const float4* row4 = (const float4*)(g_scores + (size_t)b * NKEYS + c * CHUNK);
    const int nv = CHUNK / 4;          // 6250
    const int gbase = c * CHUNK;

    float ts[TOPK];
    int   ti[TOPK];
    #pragma unroll
    for (int j = 0; j < TOPK; ++j) { ts[j] = -CUDART_INF_F; ti[j] = 0; }

    for (int v = tid; v < nv; v += SCAN_T) {
        float4 f = row4[v];
        int gi = gbase + 4 * v;
        float e[4] = { f.x, f.y, f.z, f.w };
        #pragma unroll
        for (int q = 0; q < 4; ++q) {
            float s = e[q];
            if (s > ts[TOPK - 1]) {
                float cs = s; int ci = gi + q;
                #pragma unroll
                for (int j = 0; j < TOPK; ++j) {
                    if (cs > ts[j]) {
                        float tf = ts[j]; ts[j] = cs; cs = tf;
                        int   t2 = ti[j]; ti[j] = ci; ci = t2;
                    }
                }
            }
        }
    }

    __shared__ float ss[SCAN_T * TOPK];
    __shared__ int   si[SCAN_T * TOPK];
    #pragma unroll
    for (int j = 0; j < TOPK; ++j) {
        ss[tid * TOPK + j] = ts[j];
        si[tid * TOPK + j] = ti[j];
    }
    __syncthreads();

    __shared__ float rs[SCAN_T];
    __shared__ int   rp[SCAN_T];

    for (int r = 0; r < TOPK; ++r) {
        float best = -CUDART_INF_F;
        int   bpos = 0;
        #pragma unroll
        for (int j = 0; j < TOPK; ++j) {
            int p = tid + j * SCAN_T;
            float v = ss[p];
            if (v > best) { best = v; bpos = p; }
        }
        rs[tid] = best;
        rp[tid] = bpos;
        __syncthreads();
        for (int st = SCAN_T / 2; st > 0; st >>= 1) {
            if (tid < st) {
                if (rs[tid + st] > rs[tid]) {
                    rs[tid] = rs[tid + st];
                    rp[tid] = rp[tid + st];
                }
            }
            __syncthreads();
        }
        if (tid == 0) {
            int p = rp[0];
            g_cand_s[(b * NCHUNK + c) * TOPK + r] = ss[p];
            g_cand_i[(b * NCHUNK + c) * TOPK + r] = si[p];
            ss[p] = -CUDART_INF_F;
        }
        __syncthreads();
    }
}

// ---------------------------------------------------------------------------
// Kernel 2b: merge 64 candidates per query + slot gather. 256 blocks x 256 thr.
// ---------------------------------------------------------------------------
#define NCAND (NCHUNK * TOPK)   // 64

__global__ __launch_bounds__(256) void topk_merge_gather(const float* __restrict__ slots,
                                                         float* __restrict__ out_slots,
                                                         float* __restrict__ out_scores) {
    const int b   = blockIdx.x;
    const int tid = threadIdx.x;

    __shared__ float cs[NCAND];
    __shared__ int   ci[NCAND];
    __shared__ float rs[NCAND];
    __shared__ int   rp[NCAND];
    __shared__ float wsc[TOPK];
    __shared__ int   widx[TOPK];

    if (tid < NCAND) {
        cs[tid] = g_cand_s[b * NCAND + tid];
        ci[tid] = g_cand_i[b * NCAND + tid];
    }
    __syncthreads();

    for (int r = 0; r < TOPK; ++r) {
        if (tid < NCAND) { rs[tid] = cs[tid]; rp[tid] = tid; }
        __syncthreads();
        for (int st = NCAND / 2; st > 0; st >>= 1) {
            if (tid < st) {
                if (rs[tid + st] > rs[tid]) {
                    rs[tid] = rs[tid + st];
                    rp[tid] = rp[tid + st];
                }
            }
            __syncthreads();
        }
        if (tid == 0) {
            int p = rp[0];
            wsc[r]  = cs[p];
            widx[r] = ci[p];
            cs[p] = -CUDART_INF_F;
        }
        __syncthreads();
    }

    if (tid < TOPK)
        out_scores[b * TOPK + tid] = wsc[tid];

    #pragma unroll
    for (int j = 0; j < TOPK; ++j)
        out_slots[((size_t)b * TOPK + j) * SLOT + tid] =
            slots[(size_t)widx[j] * SLOT + tid];
}

// ---------------------------------------------------------------------------
extern "C" void kernel_launch(void* const* d_in, const int* in_sizes, int n_in,
                              void* d_out, int out_size) {
    const float* Q = (const float*)d_in[0];
    const float* K = (const float*)d_in[1];
    const float* S = (const float*)d_in[2];

    float* out        = (float*)d_out;
    float* out_slots  = out;
    float* out_scores = out + (size_t)BQ * TOPK * SLOT;

    size_t smem_bytes = 2ull * DIM * PAD * sizeof(float);
    cudaFuncSetAttribute(gemm_scores, cudaFuncAttributeMaxDynamicSharedMemorySize,
                         (int)smem_bytes);

    dim3 grid((NKEYS + BN - 1) / BN, BQ / BM);
    gemm_scores<<<grid, 256, smem_bytes>>>(Q, K);
    topk_scan<<<dim3(NCHUNK, BQ), SCAN_T>>>();
    topk_merge_gather<<<BQ, 256>>>(S, out_slots, out_scores);
}

// round 4
// speedup vs baseline: 1.9068x; 1.7973x over previous
#include <cuda_runtime.h>
#include <cuda_bf16.h>
#include <math_constants.h>
#include <cstdint>

#define BQ     256
#define NKEYS  200000
#define DIM    128
#define SLOT   256
#define TOPK   8
#define NTILE  128
#define NTILES 1563          // ceil(200000/128)
#define NCTA   148
#define HALF_CTAS 74
#define THREADS 256
#define NC_PER_Q (HALF_CTAS * TOPK)   // 592 candidates per query

__device__ float g_cand_s[(size_t)BQ * NC_PER_Q];
__device__ int   g_cand_i[(size_t)BQ * NC_PER_Q];

// ---------------- smem layout (bytes) ----------------
#define TILE_B   32768          // 128 rows x 128 bf16 (256B/row), xor-swizzled
#define SM_QH    0
#define SM_QL    (SM_QH + TILE_B)
#define SM_KH    (SM_QL + TILE_B)
#define SM_KL    (SM_KH + TILE_B)
#define SM_SC    (SM_KL + TILE_B)      // scores: 128 x 136 fp32
#define SC_STRIDE 136
#define SM_TOTAL (SM_SC + 128 * SC_STRIDE * 4)   // 200704

// xor swizzle on 16B chunks within a 256B row
__device__ __forceinline__ uint32_t sw_off(int row, int chunk) {
    return (uint32_t)(row * 256 + ((((chunk) & 8) | ((chunk ^ row) & 7)) << 4));
}

__device__ __forceinline__ uint32_t smem_u32(const void* p) {
    uint32_t a;
    asm("{ .reg .u64 t; cvta.to.shared.u64 t, %1; cvt.u32.u64 %0, t; }" : "=r"(a) : "l"(p));
    return a;
}

__device__ __forceinline__ void ldsm4(uint32_t& r0, uint32_t& r1, uint32_t& r2, uint32_t& r3,
                                      uint32_t addr) {
    asm volatile("ldmatrix.sync.aligned.m8n8.x4.shared.b16 {%0,%1,%2,%3}, [%4];"
                 : "=r"(r0), "=r"(r1), "=r"(r2), "=r"(r3) : "r"(addr));
}

__device__ __forceinline__ void mma_bf16(float* c, const uint32_t* a, uint32_t b0, uint32_t b1) {
    asm volatile("mma.sync.aligned.m16n8k16.row.col.f32.bf16.bf16.f32 "
                 "{%0,%1,%2,%3},{%4,%5,%6,%7},{%8,%9},{%0,%1,%2,%3};"
                 : "+f"(c[0]), "+f"(c[1]), "+f"(c[2]), "+f"(c[3])
                 : "r"(a[0]), "r"(a[1]), "r"(a[2]), "r"(a[3]), "r"(b0), "r"(b1));
}

// split float4 -> bf16 hi (truncate) + bf16 lo (residual, rn) into swizzled tiles
__device__ __forceinline__ void cvt_store(char* sm, int hi_t, int lo_t, int row, int f, float4 v) {
    uint32_t x0 = __float_as_uint(v.x), x1 = __float_as_uint(v.y);
    uint32_t x2 = __float_as_uint(v.z), x3 = __float_as_uint(v.w);
    uint32_t h01 = (x0 >> 16) | (x1 & 0xFFFF0000u);
    uint32_t h23 = (x2 >> 16) | (x3 & 0xFFFF0000u);
    float l0 = v.x - __uint_as_float(x0 & 0xFFFF0000u);
    float l1 = v.y - __uint_as_float(x1 & 0xFFFF0000u);
    float l2 = v.z - __uint_as_float(x2 & 0xFFFF0000u);
    float l3 = v.w - __uint_as_float(x3 & 0xFFFF0000u);
    uint32_t p01, p23;
    asm("cvt.rn.satfinite.bf16x2.f32 %0, %1, %2;" : "=r"(p01) : "f"(l1), "f"(l0));
    asm("cvt.rn.satfinite.bf16x2.f32 %0, %1, %2;" : "=r"(p23) : "f"(l3), "f"(l2));
    uint32_t off = sw_off(row, f >> 1) + (f & 1) * 8;
    *(uint2*)(sm + hi_t + off) = make_uint2(h01, h23);
    *(uint2*)(sm + lo_t + off) = make_uint2(p01, p23);
}

__device__ __forceinline__ void ins8(float (&ts)[TOPK], int (&ti)[TOPK], float s, int idx) {
    if (s > ts[TOPK - 1]) {
        #pragma unroll
        for (int j = 0; j < TOPK; ++j) {
            if (s > ts[j]) {
                float tf = ts[j]; ts[j] = s; s = tf;
                int   t2 = ti[j]; ti[j] = idx; idx = t2;
            }
        }
    }
}

// ---------------------------------------------------------------------------
// Kernel 1: persistent bf16 hi/lo mma.sync GEMM + fused per-CTA top-8
// ---------------------------------------------------------------------------
__global__ __launch_bounds__(THREADS, 1) void gemm_topk(const float* __restrict__ Q,
                                                        const float* __restrict__ K) {
    extern __shared__ char sm[];
    const uint32_t smb = smem_u32(sm);
    float* ss = (float*)(sm + SM_SC);

    const int tid  = threadIdx.x;
    const int lane = tid & 31;
    const int wid  = tid >> 5;
    const int wm   = wid >> 1;          // 0..3 (M)
    const int wn   = wid & 1;           // 0..1 (N)

    const int cta = blockIdx.x;
    const int h   = (cta < HALF_CTAS) ? 0 : 1;            // query half
    const int cl  = cta - h * HALF_CTAS;                  // 0..73

    // ---- stage Q half (rows h*128 .. +128) as hi/lo bf16 ----
    const float4* Q4 = (const float4*)Q;
    #pragma unroll
    for (int i = 0; i < 16; ++i) {
        int v = tid + i * 256;
        int r = v >> 5, f = v & 31;
        cvt_store(sm, SM_QH, SM_QL, r, f, Q4[(size_t)(h * 128 + r) * 32 + f]);
    }

    // per-thread running top-8 (this thread owns row = tid>>1, cols half tid&1)
    const int srow  = tid >> 1;
    const int shalf = tid & 1;
    float ts[TOPK];
    int   ti[TOPK];
    #pragma unroll
    for (int j = 0; j < TOPK; ++j) { ts[j] = -CUDART_INF_F; ti[j] = 0; }

    const float4* K4 = (const float4*)K;

    // precomputed ldmatrix lane address components
    const int a_r = (lane & 15);
    const int a_c = (lane >> 4);
    const int b_r = (lane & 7) + ((lane >> 4) << 3);
    const int b_c = (lane >> 3) & 1;

    for (int t = cl; t < NTILES; t += HALF_CTAS) {
        const int n_base = t * NTILE;

        // ---- load + split K tile ----
        #pragma unroll
        for (int i = 0; i < 16; ++i) {
            int v = tid + i * 256;
            int r = v >> 5, f = v & 31;
            int gn = n_base + r;
            float4 kv = make_float4(0.f, 0.f, 0.f, 0.f);
            if (gn < NKEYS) kv = K4[(size_t)gn * 32 + f];
            cvt_store(sm, SM_KH, SM_KL, r, f, kv);
        }
        __syncthreads();

        // ---- MMA: warp tile 32(M) x 64(N), 3 passes fused per k-step ----
        float acc[2][8][4];
        #pragma unroll
        for (int mt = 0; mt < 2; ++mt)
            #pragma unroll
            for (int nt = 0; nt < 8; ++nt)
                #pragma unroll
                for (int e = 0; e < 4; ++e)
                    acc[mt][nt][e] = 0.f;

        #pragma unroll
        for (int ks = 0; ks < 8; ++ks) {
            uint32_t aH[2][4], aL[2][4];
            #pragma unroll
            for (int mt = 0; mt < 2; ++mt) {
                int row = wm * 32 + mt * 16 + a_r;
                uint32_t off = sw_off(row, ks * 2 + a_c);
                ldsm4(aH[mt][0], aH[mt][1], aH[mt][2], aH[mt][3], smb + SM_QH + off);
                ldsm4(aL[mt][0], aL[mt][1], aL[mt][2], aL[mt][3], smb + SM_QL + off);
            }
            uint32_t bH[16], bL[16];
            #pragma unroll
            for (int p = 0; p < 4; ++p) {
                int row = wn * 64 + p * 16 + b_r;
                uint32_t off = sw_off(row, ks * 2 + b_c);
                ldsm4(bH[p*4+0], bH[p*4+1], bH[p*4+2], bH[p*4+3], smb + SM_KH + off);
                ldsm4(bL[p*4+0], bL[p*4+1], bL[p*4+2], bL[p*4+3], smb + SM_KL + off);
            }
            #pragma unroll
            for (int mt = 0; mt < 2; ++mt)
                #pragma unroll
                for (int nt = 0; nt < 8; ++nt) {
                    uint32_t h0 = bH[nt*2], h1 = bH[nt*2+1];
                    uint32_t l0 = bL[nt*2], l1 = bL[nt*2+1];
                    mma_bf16(acc[mt][nt], aH[mt], h0, h1);   // Qh*Kh
                    mma_bf16(acc[mt][nt], aH[mt], l0, l1);   // Qh*Kl
                    mma_bf16(acc[mt][nt], aL[mt], h0, h1);   // Ql*Kh
                }
        }

        // ---- scores -> smem ----
        {
            int g = lane >> 2, tq = lane & 3;
            #pragma unroll
            for (int mt = 0; mt < 2; ++mt) {
                int r0 = wm * 32 + mt * 16 + g;
                #pragma unroll
                for (int nt = 0; nt < 8; ++nt) {
                    int col = wn * 64 + nt * 8 + tq * 2;
                    *(float2*)&ss[r0 * SC_STRIDE + col] =
                        make_float2(acc[mt][nt][0], acc[mt][nt][1]);
                    *(float2*)&ss[(r0 + 8) * SC_STRIDE + col] =
                        make_float2(acc[mt][nt][2], acc[mt][nt][3]);
                }
            }
        }
        __syncthreads();

        // ---- scan my 64 scores of row srow ----
        {
            const float* rowp = &ss[srow * SC_STRIDE + shalf * 64];
            int n0 = n_base + shalf * 64;
            #pragma unroll
            for (int j = 0; j < 16; ++j) {
                float4 sv = *(const float4*)(rowp + j * 4);
                int ib = n0 + j * 4;
                if (ib + 3 < NKEYS) {
                    ins8(ts, ti, sv.x, ib);
                    ins8(ts, ti, sv.y, ib + 1);
                    ins8(ts, ti, sv.z, ib + 2);
                    ins8(ts, ti, sv.w, ib + 3);
                } else {
                    if (ib     < NKEYS) ins8(ts, ti, sv.x, ib);
                    if (ib + 1 < NKEYS) ins8(ts, ti, sv.y, ib + 1);
                    if (ib + 2 < NKEYS) ins8(ts, ti, sv.z, ib + 2);
                    if (ib + 3 < NKEYS) ins8(ts, ti, sv.w, ib + 3);
                }
            }
        }
        // no sync needed here: next-tile K store targets K region; the
        // next score write is gated by the next __syncthreads()
    }
    __syncthreads();

    // ---- in-CTA merge: 2 threads/row -> top-8 per row ----
    float* cs = (float*)(sm + SM_SC);
    int*   ci = (int*)(sm + SM_SC + 128 * 16 * 4);
    #pragma unroll
    for (int j = 0; j < TOPK; ++j) {
        cs[srow * 16 + shalf * 8 + j] = ts[j];
        ci[srow * 16 + shalf * 8 + j] = ti[j];
    }
    __syncthreads();

    if (tid < 128) {
        float fs[TOPK];
        int   fi[TOPK];
        #pragma unroll
        for (int j = 0; j < TOPK; ++j) { fs[j] = -CUDART_INF_F; fi[j] = 0; }
        #pragma unroll
        for (int e = 0; e < 16; ++e)
            ins8(fs, fi, cs[tid * 16 + e], ci[tid * 16 + e]);
        int q = h * 128 + tid;
        #pragma unroll
        for (int j = 0; j < TOPK; ++j) {
            g_cand_s[((size_t)q * HALF_CTAS + cl) * TOPK + j] = fs[j];
            g_cand_i[((size_t)q * HALF_CTAS + cl) * TOPK + j] = fi[j];
        }
    }
}

// ---------------------------------------------------------------------------
// Kernel 2: merge 592 candidates per query + slot gather
// ---------------------------------------------------------------------------
#define MT 256
__global__ __launch_bounds__(MT) void topk_merge_gather(const float* __restrict__ slots,
                                                        float* __restrict__ out_slots,
                                                        float* __restrict__ out_scores) {
    const int b   = blockIdx.x;
    const int tid = threadIdx.x;

    float ts[TOPK];
    int   ti[TOPK];
    #pragma unroll
    for (int j = 0; j < TOPK; ++j) { ts[j] = -CUDART_INF_F; ti[j] = 0; }

    for (int i = tid; i < NC_PER_Q; i += MT)
        ins8(ts, ti, g_cand_s[(size_t)b * NC_PER_Q + i], g_cand_i[(size_t)b * NC_PER_Q + i]);

    __shared__ float sscore[MT * TOPK];
    __shared__ int   sidx[MT * TOPK];
    #pragma unroll
    for (int j = 0; j < TOPK; ++j) {
        sscore[tid * TOPK + j] = ts[j];
        sidx[tid * TOPK + j]   = ti[j];
    }
    __syncthreads();

    __shared__ float rs[MT];
    __shared__ int   rp[MT];
    __shared__ float wsc[TOPK];
    __shared__ int   widx[TOPK];

    for (int r = 0; r < TOPK; ++r) {
        float best = -CUDART_INF_F;
        int   bpos = 0;
        #pragma unroll
        for (int j = 0; j < TOPK; ++j) {
            int p = tid + j * MT;
            float v = sscore[p];
            if (v > best) { best = v; bpos = p; }
        }
        rs[tid] = best;
        rp[tid] = bpos;
        __syncthreads();
        for (int st = MT / 2; st > 0; st >>= 1) {
            if (tid < st) {
                if (rs[tid + st] > rs[tid]) {
                    rs[tid] = rs[tid + st];
                    rp[tid] = rp[tid + st];
                }
            }
            __syncthreads();
        }
        if (tid == 0) {
            int p = rp[0];
            wsc[r]  = sscore[p];
            widx[r] = sidx[p];
            sscore[p] = -CUDART_INF_F;
        }
        __syncthreads();
    }

    if (tid < TOPK)
        out_scores[b * TOPK + tid] = wsc[tid];

    #pragma unroll
    for (int j = 0; j < TOPK; ++j)
        out_slots[((size_t)b * TOPK + j) * SLOT + tid] =
            slots[(size_t)widx[j] * SLOT + tid];
}

// ---------------------------------------------------------------------------
extern "C" void kernel_launch(void* const* d_in, const int* in_sizes, int n_in,
                              void* d_out, int out_size) {
    const float* Q = (const float*)d_in[0];
    const float* K = (const float*)d_in[1];
    const float* S = (const float*)d_in[2];

    float* out        = (float*)d_out;
    float* out_slots  = out;                              // [256, 8, 256]
    float* out_scores = out + (size_t)BQ * TOPK * SLOT;   // [256, 8]

    cudaFuncSetAttribute(gemm_topk, cudaFuncAttributeMaxDynamicSharedMemorySize, SM_TOTAL);
    gemm_topk<<<NCTA, THREADS, SM_TOTAL>>>(Q, K);
    topk_merge_gather<<<BQ, MT>>>(S, out_slots, out_scores);
}

// round 5
// speedup vs baseline: 2.4523x; 1.2860x over previous
#include <cuda_runtime.h>
#include <cuda_bf16.h>
#include <math_constants.h>
#include <cstdint>

#define BQ     256
#define NKEYS  200000
#define DIM    128
#define SLOT   256
#define TOPK   8
#define NTILE  128
#define NTILES 1563          // ceil(200000/128)
#define NCTA   148
#define HALF_CTAS 74
#define THREADS 256
#define NC_PER_Q (HALF_CTAS * TOPK)   // 592 approx candidates per query

__device__ float g_cand_s[(size_t)BQ * NC_PER_Q];
__device__ int   g_cand_i[(size_t)BQ * NC_PER_Q];

// ---------------- smem layout (bytes) ----------------
#define TILE_B   32768          // 128 rows x 128 bf16 (256B/row), xor-swizzled
#define SM_QH    0
#define SM_KH    (SM_QH + TILE_B)
#define SM_SC    (SM_KH + TILE_B)      // scores: 128 x 136 fp32
#define SC_STRIDE 136
#define SM_TOTAL (SM_SC + 128 * SC_STRIDE * 4)   // 135168

// xor swizzle on 16B chunks within a 256B row (16 chunks/row)
__device__ __forceinline__ uint32_t sw_off(int row, int chunk) {
    return (uint32_t)(row * 256 + ((((chunk) & 8) | ((chunk ^ row) & 7)) << 4));
}

__device__ __forceinline__ uint32_t smem_u32(const void* p) {
    uint32_t a;
    asm("{ .reg .u64 t; cvta.to.shared.u64 t, %1; cvt.u32.u64 %0, t; }" : "=r"(a) : "l"(p));
    return a;
}

__device__ __forceinline__ void ldsm4(uint32_t& r0, uint32_t& r1, uint32_t& r2, uint32_t& r3,
                                      uint32_t addr) {
    asm volatile("ldmatrix.sync.aligned.m8n8.x4.shared.b16 {%0,%1,%2,%3}, [%4];"
                 : "=r"(r0), "=r"(r1), "=r"(r2), "=r"(r3) : "r"(addr));
}

__device__ __forceinline__ void mma_bf16(float* c, const uint32_t* a, uint32_t b0, uint32_t b1) {
    asm volatile("mma.sync.aligned.m16n8k16.row.col.f32.bf16.bf16.f32 "
                 "{%0,%1,%2,%3},{%4,%5,%6,%7},{%8,%9},{%0,%1,%2,%3};"
                 : "+f"(c[0]), "+f"(c[1]), "+f"(c[2]), "+f"(c[3])
                 : "r"(a[0]), "r"(a[1]), "r"(a[2]), "r"(a[3]), "r"(b0), "r"(b1));
}

// fp32 float4 -> bf16x2 pair (round-nearest), store 8B into swizzled tile
__device__ __forceinline__ void cvt_store(char* sm, int tile, int row, int f, float4 v) {
    uint32_t p01, p23;
    asm("cvt.rn.satfinite.bf16x2.f32 %0, %1, %2;" : "=r"(p01) : "f"(v.y), "f"(v.x));
    asm("cvt.rn.satfinite.bf16x2.f32 %0, %1, %2;" : "=r"(p23) : "f"(v.w), "f"(v.z));
    uint32_t off = sw_off(row, f >> 1) + (f & 1) * 8;
    *(uint2*)(sm + tile + off) = make_uint2(p01, p23);
}

__device__ __forceinline__ void ins8(float (&ts)[TOPK], int (&ti)[TOPK], float s, int idx) {
    if (s > ts[TOPK - 1]) {
        #pragma unroll
        for (int j = 0; j < TOPK; ++j) {
            if (s > ts[j]) {
                float tf = ts[j]; ts[j] = s; s = tf;
                int   t2 = ti[j]; ti[j] = idx; idx = t2;
            }
        }
    }
}

// ---------------------------------------------------------------------------
// Kernel 1: persistent single-pass bf16 mma.sync GEMM + fused per-CTA top-8
// ---------------------------------------------------------------------------
__global__ __launch_bounds__(THREADS, 1) void gemm_topk(const float* __restrict__ Q,
                                                        const float* __restrict__ K) {
    extern __shared__ char sm[];
    const uint32_t smb = smem_u32(sm);
    float* ss = (float*)(sm + SM_SC);

    const int tid  = threadIdx.x;
    const int lane = tid & 31;
    const int wid  = tid >> 5;
    const int wm   = wid >> 1;          // 0..3 (M)
    const int wn   = wid & 1;           // 0..1 (N)

    const int cta = blockIdx.x;
    const int h   = (cta < HALF_CTAS) ? 0 : 1;            // query half
    const int cl  = cta - h * HALF_CTAS;                  // 0..73

    // ---- stage Q half (rows h*128 .. +128) as bf16 ----
    const float4* Q4 = (const float4*)Q;
    #pragma unroll
    for (int i = 0; i < 16; ++i) {
        int v = tid + i * 256;
        int r = v >> 5, f = v & 31;
        cvt_store(sm, SM_QH, r, f, Q4[(size_t)(h * 128 + r) * 32 + f]);
    }

    const int srow  = tid >> 1;
    const int shalf = tid & 1;
    float ts[TOPK];
    int   ti[TOPK];
    #pragma unroll
    for (int j = 0; j < TOPK; ++j) { ts[j] = -CUDART_INF_F; ti[j] = 0; }

    const float4* K4 = (const float4*)K;

    // ldmatrix lane address components
    const int a_r = (lane & 15);
    const int a_c = (lane >> 4);
    const int b_r = (lane & 7) + ((lane >> 4) << 3);
    const int b_c = (lane >> 3) & 1;

    // load mapping for K tiles
    const int lr = tid >> 5;        // row base (0..7), +8 per iter
    const int lf = tid & 31;        // float4 within row

    // ---- prologue: prefetch first tile into registers ----
    float4 pf[16];
    {
        int n_base = cl * NTILE;
        #pragma unroll
        for (int i = 0; i < 16; ++i) {
            int gn = n_base + lr + i * 8;
            pf[i] = (gn < NKEYS) ? K4[(size_t)gn * 32 + lf] : make_float4(0.f, 0.f, 0.f, 0.f);
        }
    }

    for (int t = cl; t < NTILES; t += HALF_CTAS) {
        const int n_base = t * NTILE;

        // ---- commit prefetched tile to smem (bf16) ----
        #pragma unroll
        for (int i = 0; i < 16; ++i)
            cvt_store(sm, SM_KH, lr + i * 8, lf, pf[i]);
        __syncthreads();

        // ---- prefetch next tile (overlaps with MMA + scan) ----
        {
            int tn = t + HALF_CTAS;
            if (tn < NTILES) {
                int nb = tn * NTILE;
                #pragma unroll
                for (int i = 0; i < 16; ++i) {
                    int gn = nb + lr + i * 8;
                    pf[i] = (gn < NKEYS) ? K4[(size_t)gn * 32 + lf]
                                         : make_float4(0.f, 0.f, 0.f, 0.f);
                }
            }
        }

        // ---- MMA: warp tile 32(M) x 64(N), single bf16 pass ----
        float acc[2][8][4];
        #pragma unroll
        for (int mt = 0; mt < 2; ++mt)
            #pragma unroll
            for (int nt = 0; nt < 8; ++nt)
                #pragma unroll
                for (int e = 0; e < 4; ++e)
                    acc[mt][nt][e] = 0.f;

        #pragma unroll
        for (int ks = 0; ks < 8; ++ks) {
            uint32_t a[2][4];
            #pragma unroll
            for (int mt = 0; mt < 2; ++mt) {
                uint32_t off = sw_off(wm * 32 + mt * 16 + a_r, ks * 2 + a_c);
                ldsm4(a[mt][0], a[mt][1], a[mt][2], a[mt][3], smb + SM_QH + off);
            }
            uint32_t b[16];
            #pragma unroll
            for (int p = 0; p < 4; ++p) {
                uint32_t off = sw_off(wn * 64 + p * 16 + b_r, ks * 2 + b_c);
                ldsm4(b[p*4+0], b[p*4+1], b[p*4+2], b[p*4+3], smb + SM_KH + off);
            }
            #pragma unroll
            for (int mt = 0; mt < 2; ++mt)
                #pragma unroll
                for (int nt = 0; nt < 8; ++nt)
                    mma_bf16(acc[mt][nt], a[mt], b[nt*2], b[nt*2+1]);
        }

        // ---- scores -> smem ----
        {
            int g = lane >> 2, tq = lane & 3;
            #pragma unroll
            for (int mt = 0; mt < 2; ++mt) {
                int r0 = wm * 32 + mt * 16 + g;
                #pragma unroll
                for (int nt = 0; nt < 8; ++nt) {
                    int col = wn * 64 + nt * 8 + tq * 2;
                    *(float2*)&ss[r0 * SC_STRIDE + col] =
                        make_float2(acc[mt][nt][0], acc[mt][nt][1]);
                    *(float2*)&ss[(r0 + 8) * SC_STRIDE + col] =
                        make_float2(acc[mt][nt][2], acc[mt][nt][3]);
                }
            }
        }
        __syncthreads();

        // ---- scan my 64 scores of row srow (hides prefetch latency too) ----
        {
            const float* rowp = &ss[srow * SC_STRIDE + shalf * 64];
            int n0 = n_base + shalf * 64;
            #pragma unroll
            for (int j = 0; j < 16; ++j) {
                float4 sv = *(const float4*)(rowp + j * 4);
                int ib = n0 + j * 4;
                if (ib + 3 < NKEYS) {
                    ins8(ts, ti, sv.x, ib);
                    ins8(ts, ti, sv.y, ib + 1);
                    ins8(ts, ti, sv.z, ib + 2);
                    ins8(ts, ti, sv.w, ib + 3);
                } else {
                    if (ib     < NKEYS) ins8(ts, ti, sv.x, ib);
                    if (ib + 1 < NKEYS) ins8(ts, ti, sv.y, ib + 1);
                    if (ib + 2 < NKEYS) ins8(ts, ti, sv.z, ib + 2);
                    if (ib + 3 < NKEYS) ins8(ts, ti, sv.w, ib + 3);
                }
            }
        }
    }
    __syncthreads();

    // ---- in-CTA merge: 2 threads/row -> top-8 per row ----
    float* cs = (float*)(sm + SM_SC);
    int*   ci = (int*)(sm + SM_SC + 128 * 16 * 4);
    #pragma unroll
    for (int j = 0; j < TOPK; ++j) {
        cs[srow * 16 + shalf * 8 + j] = ts[j];
        ci[srow * 16 + shalf * 8 + j] = ti[j];
    }
    __syncthreads();

    if (tid < 128) {
        float fs[TOPK];
        int   fi[TOPK];
        #pragma unroll
        for (int j = 0; j < TOPK; ++j) { fs[j] = -CUDART_INF_F; fi[j] = 0; }
        #pragma unroll
        for (int e = 0; e < 16; ++e)
            ins8(fs, fi, cs[tid * 16 + e], ci[tid * 16 + e]);
        int q = h * 128 + tid;
        #pragma unroll
        for (int j = 0; j < TOPK; ++j) {
            g_cand_s[((size_t)q * HALF_CTAS + cl) * TOPK + j] = fs[j];
            g_cand_i[((size_t)q * HALF_CTAS + cl) * TOPK + j] = fi[j];
        }
    }
}

// ---------------------------------------------------------------------------
// Kernel 2: approx-merge 592 -> margin set -> exact fp32 rescore -> top-8 +
// slot gather.  One block per query, 256 threads.
// ---------------------------------------------------------------------------
#define MT 256
#define LCAP 64
__global__ __launch_bounds__(MT) void topk_rescore_gather(const float* __restrict__ Q,
                                                          const float* __restrict__ K,
                                                          const float* __restrict__ slots,
                                                          float* __restrict__ out_slots,
                                                          float* __restrict__ out_scores) {
    const int b    = blockIdx.x;
    const int tid  = threadIdx.x;
    const int lane = tid & 31;
    const int wrp  = tid >> 5;

    __shared__ float qrow[DIM];
    if (tid < DIM) qrow[tid] = Q[(size_t)b * DIM + tid];

    // ---- per-thread approx top-8 over stride ----
    float ts[TOPK];
    int   ti[TOPK];
    #pragma unroll
    for (int j = 0; j < TOPK; ++j) { ts[j] = -CUDART_INF_F; ti[j] = 0; }
    for (int i = tid; i < NC_PER_Q; i += MT)
        ins8(ts, ti, g_cand_s[(size_t)b * NC_PER_Q + i], g_cand_i[(size_t)b * NC_PER_Q + i]);

    __shared__ float sscore[MT * TOPK];
    __shared__ int   sidx[MT * TOPK];
    #pragma unroll
    for (int j = 0; j < TOPK; ++j) {
        sscore[tid * TOPK + j] = ts[j];
        sidx[tid * TOPK + j]   = ti[j];
    }
    __syncthreads();

    __shared__ float rs[MT];
    __shared__ int   rp[MT];
    __shared__ float thresh;

    // approx top-8 (only need the 8th value as threshold anchor)
    for (int r = 0; r < TOPK; ++r) {
        float best = -CUDART_INF_F;
        int   bpos = 0;
        #pragma unroll
        for (int j = 0; j < TOPK; ++j) {
            int p = tid + j * MT;
            float v = sscore[p];
            if (v > best) { best = v; bpos = p; }
        }
        rs[tid] = best;
        rp[tid] = bpos;
        __syncthreads();
        for (int st = MT / 2; st > 0; st >>= 1) {
            if (tid < st) {
                if (rs[tid + st] > rs[tid]) {
                    rs[tid] = rs[tid + st];
                    rp[tid] = rp[tid + st];
                }
            }
            __syncthreads();
        }
        if (tid == 0) {
            int p = rp[0];
            if (r == TOPK - 1) thresh = sscore[p] - 0.25f;   // margin vs bf16 error
            sscore[p] = -CUDART_INF_F;
        }
        __syncthreads();
    }

    // ---- compact margin set from the original candidate pool ----
    __shared__ int   lcnt;
    __shared__ int   li[LCAP];
    __shared__ float es[LCAP];
    if (tid == 0) lcnt = 0;
    __syncthreads();
    float tau = thresh;
    for (int i = tid; i < NC_PER_Q; i += MT) {
        float s = g_cand_s[(size_t)b * NC_PER_Q + i];
        if (s >= tau) {
            int p = atomicAdd(&lcnt, 1);
            if (p < LCAP) li[p] = g_cand_i[(size_t)b * NC_PER_Q + i];
        }
    }
    __syncthreads();
    int n = lcnt < LCAP ? lcnt : LCAP;

    // ---- exact fp32 rescore: one warp per candidate ----
    const float4* K4 = (const float4*)K;
    for (int c = wrp; c < n; c += 8) {
        float4 kv = K4[(size_t)li[c] * 32 + lane];
        float4 qv = *(const float4*)&qrow[lane * 4];
        float d = kv.x * qv.x + kv.y * qv.y + kv.z * qv.z + kv.w * qv.w;
        #pragma unroll
        for (int o = 16; o; o >>= 1) d += __shfl_xor_sync(0xFFFFFFFFu, d, o);
        if (lane == 0) es[c] = d;
    }
    __syncthreads();

    // ---- final exact top-8 ----
    __shared__ float wsc[TOPK];
    __shared__ int   widx[TOPK];
    if (tid == 0) {
        float fs[TOPK];
        int   fi[TOPK];
        #pragma unroll
        for (int j = 0; j < TOPK; ++j) { fs[j] = -CUDART_INF_F; fi[j] = 0; }
        for (int c = 0; c < n; ++c)
            ins8(fs, fi, es[c], li[c]);
        #pragma unroll
        for (int j = 0; j < TOPK; ++j) { wsc[j] = fs[j]; widx[j] = fi[j]; }
    }
    __syncthreads();

    if (tid < TOPK)
        out_scores[b * TOPK + tid] = wsc[tid];

    #pragma unroll
    for (int j = 0; j < TOPK; ++j)
        out_slots[((size_t)b * TOPK + j) * SLOT + tid] =
            slots[(size_t)widx[j] * SLOT + tid];
}

// ---------------------------------------------------------------------------
extern "C" void kernel_launch(void* const* d_in, const int* in_sizes, int n_in,
                              void* d_out, int out_size) {
    const float* Q = (const float*)d_in[0];
    const float* K = (const float*)d_in[1];
    const float* S = (const float*)d_in[2];

    float* out        = (float*)d_out;
    float* out_slots  = out;                              // [256, 8, 256]
    float* out_scores = out + (size_t)BQ * TOPK * SLOT;   // [256, 8]

    cudaFuncSetAttribute(gemm_topk, cudaFuncAttributeMaxDynamicSharedMemorySize, SM_TOTAL);
    gemm_topk<<<NCTA, THREADS, SM_TOTAL>>>(Q, K);
    topk_rescore_gather<<<BQ, MT>>>(Q, K, S, out_slots, out_scores);
}

// round 6
// speedup vs baseline: 3.3647x; 1.3721x over previous
#include <cuda_runtime.h>
#include <cuda_bf16.h>
#include <math_constants.h>
#include <cstdint>

#define BQ     256
#define NKEYS  200000
#define DIM    128
#define SLOT   256
#define TOPK   8
#define NTILE  128
#define NTILES 1563          // ceil(200000/128)
#define NCTA   148
#define HALF_CTAS 74
#define THREADS 256
#define NC_PER_Q (HALF_CTAS * TOPK)   // 592 approx candidates per query
#define TPK    4             // per-thread per-row top-4

__device__ float g_cand_s[(size_t)BQ * NC_PER_Q];
__device__ int   g_cand_i[(size_t)BQ * NC_PER_Q];
__device__ uint4 g_kb4[(size_t)NKEYS * DIM * 2 / 16];   // K as bf16, row-linear (51.2MB)

// ---------------- smem layout (bytes) ----------------
#define TILE_B   32768          // 128 rows x 128 bf16 (256B/row), xor-swizzled
#define SM_Q     0
#define SM_K0    (SM_Q  + TILE_B)
#define SM_K1    (SM_K0 + TILE_B)
#define SM_TOTAL (SM_K1 + TILE_B)    // 98304

// xor swizzle on 16B chunks within a 256B row (16 chunks/row)
__device__ __forceinline__ uint32_t sw_off(int row, int chunk) {
    return (uint32_t)(row * 256 + ((((chunk) & 8) | ((chunk ^ row) & 7)) << 4));
}

__device__ __forceinline__ uint32_t smem_u32(const void* p) {
    uint32_t a;
    asm("{ .reg .u64 t; cvta.to.shared.u64 t, %1; cvt.u32.u64 %0, t; }" : "=r"(a) : "l"(p));
    return a;
}

__device__ __forceinline__ void ldsm4(uint32_t& r0, uint32_t& r1, uint32_t& r2, uint32_t& r3,
                                      uint32_t addr) {
    asm volatile("ldmatrix.sync.aligned.m8n8.x4.shared.b16 {%0,%1,%2,%3}, [%4];"
                 : "=r"(r0), "=r"(r1), "=r"(r2), "=r"(r3) : "r"(addr));
}

__device__ __forceinline__ void mma_bf16(float* c, const uint32_t* a, uint32_t b0, uint32_t b1) {
    asm volatile("mma.sync.aligned.m16n8k16.row.col.f32.bf16.bf16.f32 "
                 "{%0,%1,%2,%3},{%4,%5,%6,%7},{%8,%9},{%0,%1,%2,%3};"
                 : "+f"(c[0]), "+f"(c[1]), "+f"(c[2]), "+f"(c[3])
                 : "r"(a[0]), "r"(a[1]), "r"(a[2]), "r"(a[3]), "r"(b0), "r"(b1));
}

__device__ __forceinline__ void cp16(uint32_t dst, const void* src, int nbytes) {
    asm volatile("cp.async.cg.shared.global [%0], [%1], 16, %2;"
                 :: "r"(dst), "l"(src), "r"(nbytes) : "memory");
}
#define CP_COMMIT() asm volatile("cp.async.commit_group;" ::: "memory")
template <int N>
__device__ __forceinline__ void cp_wait() {
    asm volatile("cp.async.wait_group %0;" :: "n"(N) : "memory");
}

// fp32 float4 -> bf16x2 pair, store 8B into swizzled tile (Q staging)
__device__ __forceinline__ void cvt_store(char* sm, int tile, int row, int f, float4 v) {
    uint32_t p01, p23;
    asm("cvt.rn.satfinite.bf16x2.f32 %0, %1, %2;" : "=r"(p01) : "f"(v.y), "f"(v.x));
    asm("cvt.rn.satfinite.bf16x2.f32 %0, %1, %2;" : "=r"(p23) : "f"(v.w), "f"(v.z));
    uint32_t off = sw_off(row, f >> 1) + (f & 1) * 8;
    *(uint2*)(sm + tile + off) = make_uint2(p01, p23);
}

__device__ __forceinline__ void ins8(float (&ts)[TOPK], int (&ti)[TOPK], float s, int idx) {
    if (s > ts[TOPK - 1]) {
        #pragma unroll
        for (int j = 0; j < TOPK; ++j) {
            if (s > ts[j]) {
                float tf = ts[j]; ts[j] = s; s = tf;
                int   t2 = ti[j]; ti[j] = idx; idx = t2;
            }
        }
    }
}

__device__ __forceinline__ void ins4(float* ts, int* ti, float s, int idx) {
    if (s > ts[TPK - 1]) {
        #pragma unroll
        for (int j = 0; j < TPK; ++j) {
            if (s > ts[j]) {
                float tf = ts[j]; ts[j] = s; s = tf;
                int   t2 = ti[j]; ti[j] = idx; idx = t2;
            }
        }
    }
}

// ---------------------------------------------------------------------------
// Kernel 0: K fp32 -> bf16 (row-linear), pure bandwidth
// ---------------------------------------------------------------------------
__global__ __launch_bounds__(256) void convert_k(const float* __restrict__ K) {
    size_t i = (size_t)blockIdx.x * 256 + threadIdx.x;   // float4 index
    const float4* K4 = (const float4*)K;
    uint2* out = (uint2*)g_kb4;
    float4 v = K4[i];
    uint32_t p01, p23;
    asm("cvt.rn.satfinite.bf16x2.f32 %0, %1, %2;" : "=r"(p01) : "f"(v.y), "f"(v.x));
    asm("cvt.rn.satfinite.bf16x2.f32 %0, %1, %2;" : "=r"(p23) : "f"(v.w), "f"(v.z));
    out[i] = make_uint2(p01, p23);
}

// ---------------------------------------------------------------------------
// Kernel 1: persistent bf16 GEMM (cp.async double-buffered) + register top-k
// ---------------------------------------------------------------------------
__global__ __launch_bounds__(THREADS, 1) void gemm_topk(const float* __restrict__ Q) {
    extern __shared__ char sm[];
    const uint32_t smb = smem_u32(sm);

    const int tid  = threadIdx.x;
    const int lane = tid & 31;
    const int wid  = tid >> 5;
    const int wm   = wid >> 1;          // 0..3 (M)
    const int wn   = wid & 1;           // 0..1 (N)

    const int cta = blockIdx.x;
    const int h   = (cta < HALF_CTAS) ? 0 : 1;            // query half
    const int cl  = cta - h * HALF_CTAS;                  // 0..73

    // ---- stage Q half as bf16 (swizzled) ----
    const float4* Q4 = (const float4*)Q;
    #pragma unroll
    for (int i = 0; i < 16; ++i) {
        int v = tid + i * 256;
        int r = v >> 5, f = v & 31;
        cvt_store(sm, SM_Q, r, f, Q4[(size_t)(h * 128 + r) * 32 + f]);
    }

    // ldmatrix lane address components
    const int a_r = (lane & 15);
    const int a_c = (lane >> 4);
    const int b_r = (lane & 7) + ((lane >> 4) << 3);
    const int b_c = (lane >> 3) & 1;
    const int g   = lane >> 2;          // row group 0..7
    const int tq  = lane & 3;

    // per-thread top-4 for each of 4 owned rows (mt,hi)
    float ts[4][TPK];
    int   ti[4][TPK];
    #pragma unroll
    for (int l = 0; l < 4; ++l)
        #pragma unroll
        for (int j = 0; j < TPK; ++j) { ts[l][j] = -CUDART_INF_F; ti[l][j] = 0; }

    // cp.async chunk mapping: 8 chunks per thread
    const char* kb = (const char*)g_kb4;

    auto issue_tile = [&](int t, int buf) {
        int n_base = t * NTILE;
        uint32_t base = smb + SM_K0 + buf * TILE_B;
        #pragma unroll
        for (int i = 0; i < 8; ++i) {
            int chunk = tid + i * 256;
            int row = chunk >> 4, cc = chunk & 15;
            int gn = n_base + row;
            int ok = gn < NKEYS;
            const void* src = kb + ((size_t)(ok ? gn : 0) * 256 + cc * 16);
            cp16(base + sw_off(row, cc), src, ok ? 16 : 0);
        }
    };

    // prologue
    issue_tile(cl, 0);
    CP_COMMIT();

    int j = 0;
    for (int t = cl; t < NTILES; t += HALF_CTAS, ++j) {
        const int n_base = t * NTILE;
        int tn = t + HALF_CTAS;
        if (tn < NTILES) {
            issue_tile(tn, (j + 1) & 1);
            CP_COMMIT();
            cp_wait<1>();
        } else {
            cp_wait<0>();
        }
        __syncthreads();

        const uint32_t kbase = smb + SM_K0 + (j & 1) * TILE_B;

        // ---- MMA: warp tile 32(M) x 64(N) ----
        float acc[2][8][4];
        #pragma unroll
        for (int mt = 0; mt < 2; ++mt)
            #pragma unroll
            for (int nt = 0; nt < 8; ++nt)
                #pragma unroll
                for (int e = 0; e < 4; ++e)
                    acc[mt][nt][e] = 0.f;

        #pragma unroll
        for (int ks = 0; ks < 8; ++ks) {
            uint32_t a[2][4];
            #pragma unroll
            for (int mt = 0; mt < 2; ++mt) {
                uint32_t off = sw_off(wm * 32 + mt * 16 + a_r, ks * 2 + a_c);
                ldsm4(a[mt][0], a[mt][1], a[mt][2], a[mt][3], smb + SM_Q + off);
            }
            uint32_t b[16];
            #pragma unroll
            for (int p = 0; p < 4; ++p) {
                uint32_t off = sw_off(wn * 64 + p * 16 + b_r, ks * 2 + b_c);
                ldsm4(b[p*4+0], b[p*4+1], b[p*4+2], b[p*4+3], kbase + off);
            }
            #pragma unroll
            for (int mt = 0; mt < 2; ++mt)
                #pragma unroll
                for (int nt = 0; nt < 8; ++nt)
                    mma_bf16(acc[mt][nt], a[mt], b[nt*2], b[nt*2+1]);
        }

        // ---- scan accumulators in registers ----
        if (n_base + NTILE <= NKEYS) {
            #pragma unroll
            for (int mt = 0; mt < 2; ++mt)
                #pragma unroll
                for (int hi = 0; hi < 2; ++hi) {
                    float* lts = ts[mt * 2 + hi];
                    int*   lti = ti[mt * 2 + hi];
                    #pragma unroll
                    for (int nt = 0; nt < 8; ++nt) {
                        int n0 = n_base + wn * 64 + nt * 8 + tq * 2;
                        ins4(lts, lti, acc[mt][nt][hi * 2 + 0], n0);
                        ins4(lts, lti, acc[mt][nt][hi * 2 + 1], n0 + 1);
                    }
                }
        } else {
            #pragma unroll
            for (int mt = 0; mt < 2; ++mt)
                #pragma unroll
                for (int hi = 0; hi < 2; ++hi) {
                    float* lts = ts[mt * 2 + hi];
                    int*   lti = ti[mt * 2 + hi];
                    #pragma unroll
                    for (int nt = 0; nt < 8; ++nt) {
                        int n0 = n_base + wn * 64 + nt * 8 + tq * 2;
                        if (n0     < NKEYS) ins4(lts, lti, acc[mt][nt][hi * 2 + 0], n0);
                        if (n0 + 1 < NKEYS) ins4(lts, lti, acc[mt][nt][hi * 2 + 1], n0 + 1);
                    }
                }
        }
        __syncthreads();   // protect smem K buf before next overwrite
    }

    // ---- CTA merge: 32 candidates per row -> top-8 per row ----
    // reuse smem: scores [128][32] fp32 at 0, idx at 16KB
    float* cs = (float*)sm;
    int*   ci = (int*)(sm + 16384);
    #pragma unroll
    for (int mt = 0; mt < 2; ++mt)
        #pragma unroll
        for (int hi = 0; hi < 2; ++hi) {
            int row = wm * 32 + mt * 16 + hi * 8 + g;
            int slot = (wn * 4 + tq) * TPK;
            #pragma unroll
            for (int j2 = 0; j2 < TPK; ++j2) {
                cs[row * 32 + slot + j2] = ts[mt * 2 + hi][j2];
                ci[row * 32 + slot + j2] = ti[mt * 2 + hi][j2];
            }
        }
    __syncthreads();

    if (tid < 128) {
        float fs[TOPK];
        int   fi[TOPK];
        #pragma unroll
        for (int j2 = 0; j2 < TOPK; ++j2) { fs[j2] = -CUDART_INF_F; fi[j2] = 0; }
        #pragma unroll
        for (int e = 0; e < 32; ++e)
            ins8(fs, fi, cs[tid * 32 + e], ci[tid * 32 + e]);
        int q = h * 128 + tid;
        #pragma unroll
        for (int j2 = 0; j2 < TOPK; ++j2) {
            g_cand_s[((size_t)q * HALF_CTAS + cl) * TOPK + j2] = fs[j2];
            g_cand_i[((size_t)q * HALF_CTAS + cl) * TOPK + j2] = fi[j2];
        }
    }
}

// ---------------------------------------------------------------------------
// Kernel 2: approx-merge 592 -> margin set -> exact fp32 rescore -> top-8 +
// slot gather.  One block per query, 256 threads.
// ---------------------------------------------------------------------------
#define MT 256
#define LCAP 64
__global__ __launch_bounds__(MT) void topk_rescore_gather(const float* __restrict__ Q,
                                                          const float* __restrict__ K,
                                                          const float* __restrict__ slots,
                                                          float* __restrict__ out_slots,
                                                          float* __restrict__ out_scores) {
    const int b    = blockIdx.x;
    const int tid  = threadIdx.x;
    const int lane = tid & 31;
    const int wrp  = tid >> 5;

    __shared__ float qrow[DIM];
    if (tid < DIM) qrow[tid] = Q[(size_t)b * DIM + tid];

    float ts[TOPK];
    int   ti[TOPK];
    #pragma unroll
    for (int j = 0; j < TOPK; ++j) { ts[j] = -CUDART_INF_F; ti[j] = 0; }
    for (int i = tid; i < NC_PER_Q; i += MT)
        ins8(ts, ti, g_cand_s[(size_t)b * NC_PER_Q + i], g_cand_i[(size_t)b * NC_PER_Q + i]);

    __shared__ float sscore[MT * TOPK];
    #pragma unroll
    for (int j = 0; j < TOPK; ++j)
        sscore[tid * TOPK + j] = ts[j];
    __syncthreads();

    __shared__ float rs[MT];
    __shared__ int   rp[MT];
    __shared__ float thresh;

    for (int r = 0; r < TOPK; ++r) {
        float best = -CUDART_INF_F;
        int   bpos = 0;
        #pragma unroll
        for (int j = 0; j < TOPK; ++j) {
            int p = tid + j * MT;
            float v = sscore[p];
            if (v > best) { best = v; bpos = p; }
        }
        rs[tid] = best;
        rp[tid] = bpos;
        __syncthreads();
        for (int st = MT / 2; st > 0; st >>= 1) {
            if (tid < st) {
                if (rs[tid + st] > rs[tid]) {
                    rs[tid] = rs[tid + st];
                    rp[tid] = rp[tid + st];
                }
            }
            __syncthreads();
        }
        if (tid == 0) {
            int p = rp[0];
            if (r == TOPK - 1) thresh = sscore[p] - 0.25f;
            sscore[p] = -CUDART_INF_F;
        }
        __syncthreads();
    }

    __shared__ int   lcnt;
    __shared__ int   li[LCAP];
    __shared__ float es[LCAP];
    if (tid == 0) lcnt = 0;
    __syncthreads();
    float tau = thresh;
    for (int i = tid; i < NC_PER_Q; i += MT) {
        float s = g_cand_s[(size_t)b * NC_PER_Q + i];
        if (s >= tau) {
            int p = atomicAdd(&lcnt, 1);
            if (p < LCAP) li[p] = g_cand_i[(size_t)b * NC_PER_Q + i];
        }
    }
    __syncthreads();
    int n = lcnt < LCAP ? lcnt : LCAP;

    const float4* K4 = (const float4*)K;
    for (int c = wrp; c < n; c += 8) {
        float4 kv = K4[(size_t)li[c] * 32 + lane];
        float4 qv = *(const float4*)&qrow[lane * 4];
        float d = kv.x * qv.x + kv.y * qv.y + kv.z * qv.z + kv.w * qv.w;
        #pragma unroll
        for (int o = 16; o; o >>= 1) d += __shfl_xor_sync(0xFFFFFFFFu, d, o);
        if (lane == 0) es[c] = d;
    }
    __syncthreads();

    __shared__ float wsc[TOPK];
    __shared__ int   widx[TOPK];
    if (tid == 0) {
        float fs[TOPK];
        int   fi[TOPK];
        #pragma unroll
        for (int j = 0; j < TOPK; ++j) { fs[j] = -CUDART_INF_F; fi[j] = 0; }
        for (int c = 0; c < n; ++c)
            ins8(fs, fi, es[c], li[c]);
        #pragma unroll
        for (int j = 0; j < TOPK; ++j) { wsc[j] = fs[j]; widx[j] = fi[j]; }
    }
    __syncthreads();

    if (tid < TOPK)
        out_scores[b * TOPK + tid] = wsc[tid];

    #pragma unroll
    for (int j = 0; j < TOPK; ++j)
        out_slots[((size_t)b * TOPK + j) * SLOT + tid] =
            slots[(size_t)widx[j] * SLOT + tid];
}

// ---------------------------------------------------------------------------
extern "C" void kernel_launch(void* const* d_in, const int* in_sizes, int n_in,
                              void* d_out, int out_size) {
    const float* Q = (const float*)d_in[0];
    const float* K = (const float*)d_in[1];
    const float* S = (const float*)d_in[2];

    float* out        = (float*)d_out;
    float* out_slots  = out;                              // [256, 8, 256]
    float* out_scores = out + (size_t)BQ * TOPK * SLOT;   // [256, 8]

    convert_k<<<(NKEYS * DIM / 4) / 256, 256>>>(K);       // 25000 blocks

    cudaFuncSetAttribute(gemm_topk, cudaFuncAttributeMaxDynamicSharedMemorySize, SM_TOTAL);
    gemm_topk<<<NCTA, THREADS, SM_TOTAL>>>(Q);
    topk_rescore_gather<<<BQ, MT>>>(Q, K, S, out_slots, out_scores);
}

// round 7
// speedup vs baseline: 4.5300x; 1.3463x over previous
#include <cuda_runtime.h>
#include <cuda_bf16.h>
#include <math_constants.h>
#include <cstdint>

#define BQ     256
#define NKEYS  200000
#define DIM    128
#define SLOT   256
#define TOPK   8
#define NTILE  128
#define NTILES 1563          // ceil(200000/128)
#define NCTA   296           // 2 CTAs per SM
#define HALF_CTAS 148
#define THREADS 256
#define NC_PER_Q (HALF_CTAS * TOPK)   // 1184 approx candidates per query
#define TPK    3             // per-thread per-row top-3

__device__ float g_cand_s[(size_t)BQ * NC_PER_Q];
__device__ int   g_cand_i[(size_t)BQ * NC_PER_Q];
__device__ uint4 g_kb4[(size_t)NKEYS * DIM * 2 / 16];   // K as bf16, row-linear (51.2MB)

// ---------------- smem layout (bytes) ----------------
#define TILE_B   32768          // 128 rows x 128 bf16 (256B/row), xor-swizzled
#define SM_Q     0
#define SM_K0    (SM_Q  + TILE_B)
#define SM_K1    (SM_K0 + TILE_B)
#define SM_TOTAL (SM_K1 + TILE_B)    // 98304  (x2 CTAs = 192KB/SM, fits)

// xor swizzle on 16B chunks within a 256B row (16 chunks/row)
__device__ __forceinline__ uint32_t sw_off(int row, int chunk) {
    return (uint32_t)(row * 256 + ((((chunk) & 8) | ((chunk ^ row) & 7)) << 4));
}

__device__ __forceinline__ uint32_t smem_u32(const void* p) {
    uint32_t a;
    asm("{ .reg .u64 t; cvta.to.shared.u64 t, %1; cvt.u32.u64 %0, t; }" : "=r"(a) : "l"(p));
    return a;
}

__device__ __forceinline__ void ldsm4(uint32_t& r0, uint32_t& r1, uint32_t& r2, uint32_t& r3,
                                      uint32_t addr) {
    asm volatile("ldmatrix.sync.aligned.m8n8.x4.shared.b16 {%0,%1,%2,%3}, [%4];"
                 : "=r"(r0), "=r"(r1), "=r"(r2), "=r"(r3) : "r"(addr));
}

__device__ __forceinline__ void mma_bf16(float* c, const uint32_t* a, uint32_t b0, uint32_t b1) {
    asm volatile("mma.sync.aligned.m16n8k16.row.col.f32.bf16.bf16.f32 "
                 "{%0,%1,%2,%3},{%4,%5,%6,%7},{%8,%9},{%0,%1,%2,%3};"
                 : "+f"(c[0]), "+f"(c[1]), "+f"(c[2]), "+f"(c[3])
                 : "r"(a[0]), "r"(a[1]), "r"(a[2]), "r"(a[3]), "r"(b0), "r"(b1));
}

__device__ __forceinline__ void cp16(uint32_t dst, const void* src, int nbytes) {
    asm volatile("cp.async.cg.shared.global [%0], [%1], 16, %2;"
                 :: "r"(dst), "l"(src), "r"(nbytes) : "memory");
}
#define CP_COMMIT() asm volatile("cp.async.commit_group;" ::: "memory")
template <int N>
__device__ __forceinline__ void cp_wait() {
    asm volatile("cp.async.wait_group %0;" :: "n"(N) : "memory");
}

// fp32 float4 -> bf16x2 pair, store 8B into swizzled tile (Q staging)
__device__ __forceinline__ void cvt_store(char* sm, int tile, int row, int f, float4 v) {
    uint32_t p01, p23;
    asm("cvt.rn.satfinite.bf16x2.f32 %0, %1, %2;" : "=r"(p01) : "f"(v.y), "f"(v.x));
    asm("cvt.rn.satfinite.bf16x2.f32 %0, %1, %2;" : "=r"(p23) : "f"(v.w), "f"(v.z));
    uint32_t off = sw_off(row, f >> 1) + (f & 1) * 8;
    *(uint2*)(sm + tile + off) = make_uint2(p01, p23);
}

__device__ __forceinline__ void ins8(float (&ts)[TOPK], int (&ti)[TOPK], float s, int idx) {
    if (s > ts[TOPK - 1]) {
        #pragma unroll
        for (int j = 0; j < TOPK; ++j) {
            if (s > ts[j]) {
                float tf = ts[j]; ts[j] = s; s = tf;
                int   t2 = ti[j]; ti[j] = idx; idx = t2;
            }
        }
    }
}

__device__ __forceinline__ void insT(float* ts, int* ti, float s, int idx) {
    if (s > ts[TPK - 1]) {
        #pragma unroll
        for (int j = 0; j < TPK; ++j) {
            if (s > ts[j]) {
                float tf = ts[j]; ts[j] = s; s = tf;
                int   t2 = ti[j]; ti[j] = idx; idx = t2;
            }
        }
    }
}

// ---------------------------------------------------------------------------
// Kernel 0: K fp32 -> bf16 (row-linear), pure bandwidth
// ---------------------------------------------------------------------------
__global__ __launch_bounds__(256) void convert_k(const float* __restrict__ K) {
    size_t i = (size_t)blockIdx.x * 256 + threadIdx.x;   // float4 index
    const float4* K4 = (const float4*)K;
    uint2* out = (uint2*)g_kb4;
    float4 v = K4[i];
    uint32_t p01, p23;
    asm("cvt.rn.satfinite.bf16x2.f32 %0, %1, %2;" : "=r"(p01) : "f"(v.y), "f"(v.x));
    asm("cvt.rn.satfinite.bf16x2.f32 %0, %1, %2;" : "=r"(p23) : "f"(v.w), "f"(v.z));
    out[i] = make_uint2(p01, p23);
}

// ---------------------------------------------------------------------------
// Kernel 1: persistent bf16 GEMM (cp.async double-buffered) + register top-k
// 2 CTAs per SM for latency hiding.
// ---------------------------------------------------------------------------
__global__ __launch_bounds__(THREADS, 2) void gemm_topk(const float* __restrict__ Q) {
    extern __shared__ char sm[];
    const uint32_t smb = smem_u32(sm);

    const int tid  = threadIdx.x;
    const int lane = tid & 31;
    const int wid  = tid >> 5;
    const int wm   = wid >> 1;          // 0..3 (M)
    const int wn   = wid & 1;           // 0..1 (N)

    const int cta = blockIdx.x;
    const int h   = (cta < HALF_CTAS) ? 0 : 1;            // query half
    const int cl  = (h == 0) ? cta : (cta - HALF_CTAS);   // 0..147

    // ---- stage Q half as bf16 (swizzled) ----
    const float4* Q4 = (const float4*)Q;
    #pragma unroll
    for (int i = 0; i < 16; ++i) {
        int v = tid + i * 256;
        int r = v >> 5, f = v & 31;
        cvt_store(sm, SM_Q, r, f, Q4[(size_t)(h * 128 + r) * 32 + f]);
    }

    // ldmatrix lane address components
    const int a_r = (lane & 15);
    const int a_c = (lane >> 4);
    const int b_r = (lane & 7) + ((lane >> 4) << 3);
    const int b_c = (lane >> 3) & 1;
    const int g   = lane >> 2;          // row group 0..7
    const int tq  = lane & 3;

    // per-thread top-3 for each of 4 owned rows (mt,hi)
    float ts[4][TPK];
    int   ti[4][TPK];
    #pragma unroll
    for (int l = 0; l < 4; ++l)
        #pragma unroll
        for (int j = 0; j < TPK; ++j) { ts[l][j] = -CUDART_INF_F; ti[l][j] = 0; }

    const char* kb = (const char*)g_kb4;

    auto issue_tile = [&](int t, int buf) {
        int n_base = t * NTILE;
        uint32_t base = smb + SM_K0 + buf * TILE_B;
        #pragma unroll
        for (int i = 0; i < 8; ++i) {
            int chunk = tid + i * 256;
            int row = chunk >> 4, cc = chunk & 15;
            int gn = n_base + row;
            int ok = gn < NKEYS;
            const void* src = kb + ((size_t)(ok ? gn : 0) * 256 + cc * 16);
            cp16(base + sw_off(row, cc), src, ok ? 16 : 0);
        }
    };

    issue_tile(cl, 0);
    CP_COMMIT();

    int j = 0;
    for (int t = cl; t < NTILES; t += HALF_CTAS, ++j) {
        const int n_base = t * NTILE;
        int tn = t + HALF_CTAS;
        if (tn < NTILES) {
            issue_tile(tn, (j + 1) & 1);
            CP_COMMIT();
            cp_wait<1>();
        } else {
            cp_wait<0>();
        }
        __syncthreads();

        const uint32_t kbase = smb + SM_K0 + (j & 1) * TILE_B;

        // ---- MMA: warp tile 32(M) x 64(N) ----
        float acc[2][8][4];
        #pragma unroll
        for (int mt = 0; mt < 2; ++mt)
            #pragma unroll
            for (int nt = 0; nt < 8; ++nt)
                #pragma unroll
                for (int e = 0; e < 4; ++e)
                    acc[mt][nt][e] = 0.f;

        #pragma unroll
        for (int ks = 0; ks < 8; ++ks) {
            uint32_t a[2][4];
            #pragma unroll
            for (int mt = 0; mt < 2; ++mt) {
                uint32_t off = sw_off(wm * 32 + mt * 16 + a_r, ks * 2 + a_c);
                ldsm4(a[mt][0], a[mt][1], a[mt][2], a[mt][3], smb + SM_Q + off);
            }
            uint32_t b[16];
            #pragma unroll
            for (int p = 0; p < 4; ++p) {
                uint32_t off = sw_off(wn * 64 + p * 16 + b_r, ks * 2 + b_c);
                ldsm4(b[p*4+0], b[p*4+1], b[p*4+2], b[p*4+3], kbase + off);
            }
            #pragma unroll
            for (int mt = 0; mt < 2; ++mt)
                #pragma unroll
                for (int nt = 0; nt < 8; ++nt)
                    mma_bf16(acc[mt][nt], a[mt], b[nt*2], b[nt*2+1]);
        }

        // ---- scan accumulators in registers ----
        if (n_base + NTILE <= NKEYS) {
            #pragma unroll
            for (int mt = 0; mt < 2; ++mt)
                #pragma unroll
                for (int hi = 0; hi < 2; ++hi) {
                    float* lts = ts[mt * 2 + hi];
                    int*   lti = ti[mt * 2 + hi];
                    #pragma unroll
                    for (int nt = 0; nt < 8; ++nt) {
                        int n0 = n_base + wn * 64 + nt * 8 + tq * 2;
                        insT(lts, lti, acc[mt][nt][hi * 2 + 0], n0);
                        insT(lts, lti, acc[mt][nt][hi * 2 + 1], n0 + 1);
                    }
                }
        } else {
            #pragma unroll
            for (int mt = 0; mt < 2; ++mt)
                #pragma unroll
                for (int hi = 0; hi < 2; ++hi) {
                    float* lts = ts[mt * 2 + hi];
                    int*   lti = ti[mt * 2 + hi];
                    #pragma unroll
                    for (int nt = 0; nt < 8; ++nt) {
                        int n0 = n_base + wn * 64 + nt * 8 + tq * 2;
                        if (n0     < NKEYS) insT(lts, lti, acc[mt][nt][hi * 2 + 0], n0);
                        if (n0 + 1 < NKEYS) insT(lts, lti, acc[mt][nt][hi * 2 + 1], n0 + 1);
                    }
                }
        }
        __syncthreads();   // protect smem K buf before next overwrite
    }

    // ---- CTA merge: 24 candidates per row -> top-8 per row ----
    float* cs = (float*)sm;
    int*   ci = (int*)(sm + 128 * 24 * 4);
    #pragma unroll
    for (int mt = 0; mt < 2; ++mt)
        #pragma unroll
        for (int hi = 0; hi < 2; ++hi) {
            int row = wm * 32 + mt * 16 + hi * 8 + g;
            int slot = (wn * 4 + tq) * TPK;
            #pragma unroll
            for (int j2 = 0; j2 < TPK; ++j2) {
                cs[row * 24 + slot + j2] = ts[mt * 2 + hi][j2];
                ci[row * 24 + slot + j2] = ti[mt * 2 + hi][j2];
            }
        }
    __syncthreads();

    if (tid < 128) {
        float fs[TOPK];
        int   fi[TOPK];
        #pragma unroll
        for (int j2 = 0; j2 < TOPK; ++j2) { fs[j2] = -CUDART_INF_F; fi[j2] = 0; }
        #pragma unroll
        for (int e = 0; e < 24; ++e)
            ins8(fs, fi, cs[tid * 24 + e], ci[tid * 24 + e]);
        int q = h * 128 + tid;
        #pragma unroll
        for (int j2 = 0; j2 < TOPK; ++j2) {
            g_cand_s[((size_t)q * HALF_CTAS + cl) * TOPK + j2] = fs[j2];
            g_cand_i[((size_t)q * HALF_CTAS + cl) * TOPK + j2] = fi[j2];
        }
    }
}

// ---------------------------------------------------------------------------
// Kernel 2: approx-merge 1184 -> margin set -> exact fp32 rescore -> top-8 +
// slot gather.  One block per query, 256 threads.
// ---------------------------------------------------------------------------
#define MT 256
#define LCAP 64
__global__ __launch_bounds__(MT) void topk_rescore_gather(const float* __restrict__ Q,
                                                          const float* __restrict__ K,
                                                          const float* __restrict__ slots,
                                                          float* __restrict__ out_slots,
                                                          float* __restrict__ out_scores) {
    const int b    = blockIdx.x;
    const int tid  = threadIdx.x;
    const int lane = tid & 31;
    const int wrp  = tid >> 5;

    __shared__ float qrow[DIM];
    if (tid < DIM) qrow[tid] = Q[(size_t)b * DIM + tid];

    float ts[TOPK];
    int   ti[TOPK];
    #pragma unroll
    for (int j = 0; j < TOPK; ++j) { ts[j] = -CUDART_INF_F; ti[j] = 0; }
    for (int i = tid; i < NC_PER_Q; i += MT)
        ins8(ts, ti, g_cand_s[(size_t)b * NC_PER_Q + i], g_cand_i[(size_t)b * NC_PER_Q + i]);

    __shared__ float sscore[MT * TOPK];
    #pragma unroll
    for (int j = 0; j < TOPK; ++j)
        sscore[tid * TOPK + j] = ts[j];
    __syncthreads();

    __shared__ float rs[MT];
    __shared__ int   rp[MT];
    __shared__ float thresh;

    for (int r = 0; r < TOPK; ++r) {
        float best = -CUDART_INF_F;
        int   bpos = 0;
        #pragma unroll
        for (int j = 0; j < TOPK; ++j) {
            int p = tid + j * MT;
            float v = sscore[p];
            if (v > best) { best = v; bpos = p; }
        }
        rs[tid] = best;
        rp[tid] = bpos;
        __syncthreads();
        for (int st = MT / 2; st > 0; st >>= 1) {
            if (tid < st) {
                if (rs[tid + st] > rs[tid]) {
                    rs[tid] = rs[tid + st];
                    rp[tid] = rp[tid + st];
                }
            }
            __syncthreads();
        }
        if (tid == 0) {
            int p = rp[0];
            if (r == TOPK - 1) thresh = sscore[p] - 0.25f;
            sscore[p] = -CUDART_INF_F;
        }
        __syncthreads();
    }

    __shared__ int   lcnt;
    __shared__ int   li[LCAP];
    __shared__ float es[LCAP];
    if (tid == 0) lcnt = 0;
    __syncthreads();
    float tau = thresh;
    for (int i = tid; i < NC_PER_Q; i += MT) {
        float s = g_cand_s[(size_t)b * NC_PER_Q + i];
        if (s >= tau) {
            int p = atomicAdd(&lcnt, 1);
            if (p < LCAP) li[p] = g_cand_i[(size_t)b * NC_PER_Q + i];
        }
    }
    __syncthreads();
    int n = lcnt < LCAP ? lcnt : LCAP;

    const float4* K4 = (const float4*)K;
    for (int c = wrp; c < n; c += 8) {
        float4 kv = K4[(size_t)li[c] * 32 + lane];
        float4 qv = *(const float4*)&qrow[lane * 4];
        float d = kv.x * qv.x + kv.y * qv.y + kv.z * qv.z + kv.w * qv.w;
        #pragma unroll
        for (int o = 16; o; o >>= 1) d += __shfl_xor_sync(0xFFFFFFFFu, d, o);
        if (lane == 0) es[c] = d;
    }
    __syncthreads();

    __shared__ float wsc[TOPK];
    __shared__ int   widx[TOPK];
    if (tid == 0) {
        float fs[TOPK];
        int   fi[TOPK];
        #pragma unroll
        for (int j = 0; j < TOPK; ++j) { fs[j] = -CUDART_INF_F; fi[j] = 0; }
        for (int c = 0; c < n; ++c)
            ins8(fs, fi, es[c], li[c]);
        #pragma unroll
        for (int j = 0; j < TOPK; ++j) { wsc[j] = fs[j]; widx[j] = fi[j]; }
    }
    __syncthreads();

    if (tid < TOPK)
        out_scores[b * TOPK + tid] = wsc[tid];

    #pragma unroll
    for (int j = 0; j < TOPK; ++j)
        out_slots[((size_t)b * TOPK + j) * SLOT + tid] =
            slots[(size_t)widx[j] * SLOT + tid];
}

// dummy launch to rotate the ncu capture slot onto gemm_topk
__global__ void profile_pad() {}

// ---------------------------------------------------------------------------
extern "C" void kernel_launch(void* const* d_in, const int* in_sizes, int n_in,
                              void* d_out, int out_size) {
    const float* Q = (const float*)d_in[0];
    const float* K = (const float*)d_in[1];
    const float* S = (const float*)d_in[2];

    float* out        = (float*)d_out;
    float* out_slots  = out;                              // [256, 8, 256]
    float* out_scores = out + (size_t)BQ * TOPK * SLOT;   // [256, 8]

    convert_k<<<(NKEYS * DIM / 4) / 256, 256>>>(K);       // 25000 blocks

    cudaFuncSetAttribute(gemm_topk, cudaFuncAttributeMaxDynamicSharedMemorySize, SM_TOTAL);
    gemm_topk<<<NCTA, THREADS, SM_TOTAL>>>(Q);
    topk_rescore_gather<<<BQ, MT>>>(Q, K, S, out_slots, out_scores);
    profile_pad<<<1, 32>>>();
}

// round 8
// speedup vs baseline: 4.9579x; 1.0945x over previous
#include <cuda_runtime.h>
#include <cuda_bf16.h>
#include <math_constants.h>
#include <cstdint>

#define BQ     256
#define NKEYS  200000
#define DIM    128
#define SLOT   256
#define TOPK   8
#define NTILE  128
#define NTILES 1563          // ceil(200000/128)
#define NCTA   296           // 2 CTAs per SM
#define HALF_CTAS 148
#define THREADS 256
#define NC_PER_Q (HALF_CTAS * TOPK)   // 1184 approx candidates per query
#define TPK    3             // per-thread per-row top-3

__device__ float g_cand_s[(size_t)BQ * NC_PER_Q];
__device__ int   g_cand_i[(size_t)BQ * NC_PER_Q];
// K as bf16, pre-swizzled per 128-row tile (32KB each), NTILES tiles
__device__ __align__(1024) uint4 g_kb4[(size_t)NTILES * 32768 / 16];

// ---------------- smem layout (bytes) ----------------
#define TILE_B   32768          // 128 rows x 128 bf16 (256B/row), xor-swizzled
#define SM_Q     0
#define SM_K0    (SM_Q  + TILE_B)
#define SM_K1    (SM_K0 + TILE_B)
#define SM_MBAR  (SM_K1 + TILE_B)          // 2 mbarriers (16B)
#define SM_TOTAL (SM_MBAR + 64)            // 98368  (x2 CTAs fits 227KB/SM)

// xor swizzle on 16B chunks within a 256B row (16 chunks/row)
__device__ __forceinline__ uint32_t sw_off(int row, int chunk) {
    return (uint32_t)(row * 256 + ((((chunk) & 8) | ((chunk ^ row) & 7)) << 4));
}

__device__ __forceinline__ uint32_t smem_u32(const void* p) {
    uint32_t a;
    asm("{ .reg .u64 t; cvta.to.shared.u64 t, %1; cvt.u32.u64 %0, t; }" : "=r"(a) : "l"(p));
    return a;
}

__device__ __forceinline__ void ldsm4(uint32_t& r0, uint32_t& r1, uint32_t& r2, uint32_t& r3,
                                      uint32_t addr) {
    asm volatile("ldmatrix.sync.aligned.m8n8.x4.shared.b16 {%0,%1,%2,%3}, [%4];"
                 : "=r"(r0), "=r"(r1), "=r"(r2), "=r"(r3) : "r"(addr));
}

__device__ __forceinline__ void mma_bf16(float* c, const uint32_t* a, uint32_t b0, uint32_t b1) {
    asm volatile("mma.sync.aligned.m16n8k16.row.col.f32.bf16.bf16.f32 "
                 "{%0,%1,%2,%3},{%4,%5,%6,%7},{%8,%9},{%0,%1,%2,%3};"
                 : "+f"(c[0]), "+f"(c[1]), "+f"(c[2]), "+f"(c[3])
                 : "r"(a[0]), "r"(a[1]), "r"(a[2]), "r"(a[3]), "r"(b0), "r"(b1));
}

#define MBAR_INIT(mb, c) asm volatile("mbarrier.init.shared.b64 [%0], %1;" :: "r"(mb), "r"(c) : "memory")
#define MBAR_EXPECT(mb, bytes) \
    asm volatile("mbarrier.arrive.expect_tx.shared.b64 _, [%0], %1;" :: "r"(mb), "r"(bytes) : "memory")
#define BULK_G2S(dst, src, bytes, mb) \
    asm volatile("cp.async.bulk.shared::cta.global.mbarrier::complete_tx::bytes [%0], [%1], %2, [%3];" \
                 :: "r"(dst), "l"(src), "r"(bytes), "r"(mb) : "memory")

__device__ __forceinline__ void mbar_wait(uint32_t mb, uint32_t parity) {
    uint32_t done;
    asm volatile("{ .reg .pred p; mbarrier.try_wait.parity.acquire.cta.shared::cta.b64 p, [%1], %2; selp.b32 %0, 1, 0, p; }"
                 : "=r"(done) : "r"(mb), "r"(parity) : "memory");
    if (!done) {
        asm volatile("{ .reg .pred P1; WL_%=: mbarrier.try_wait.parity.acquire.cta.shared::cta.b64 P1, [%0], %1, 0x989680; @P1 bra.uni WD_%=; bra.uni WL_%=; WD_%=: }"
                     :: "r"(mb), "r"(parity) : "memory");
    }
}

// fp32 float4 -> bf16x2 pair, store 8B into swizzled tile (Q staging)
__device__ __forceinline__ void cvt_store(char* sm, int tile, int row, int f, float4 v) {
    uint32_t p01, p23;
    asm("cvt.rn.satfinite.bf16x2.f32 %0, %1, %2;" : "=r"(p01) : "f"(v.y), "f"(v.x));
    asm("cvt.rn.satfinite.bf16x2.f32 %0, %1, %2;" : "=r"(p23) : "f"(v.w), "f"(v.z));
    uint32_t off = sw_off(row, f >> 1) + (f & 1) * 8;
    *(uint2*)(sm + tile + off) = make_uint2(p01, p23);
}

__device__ __forceinline__ void ins8(float (&ts)[TOPK], int (&ti)[TOPK], float s, int idx) {
    if (s > ts[TOPK - 1]) {
        #pragma unroll
        for (int j = 0; j < TOPK; ++j) {
            if (s > ts[j]) {
                float tf = ts[j]; ts[j] = s; s = tf;
                int   t2 = ti[j]; ti[j] = idx; idx = t2;
            }
        }
    }
}

__device__ __forceinline__ void insT(float* ts, int* ti, float s, int idx) {
    if (s > ts[TPK - 1]) {
        #pragma unroll
        for (int j = 0; j < TPK; ++j) {
            if (s > ts[j]) {
                float tf = ts[j]; ts[j] = s; s = tf;
                int   t2 = ti[j]; ti[j] = idx; idx = t2;
            }
        }
    }
}

// ---------------------------------------------------------------------------
// Kernel 0: K fp32 -> bf16, written in per-tile swizzled smem-image layout.
// One thread per 16B output chunk. grid = NTILES*2048/256 = 12504.
// ---------------------------------------------------------------------------
__global__ __launch_bounds__(256) void convert_k(const float* __restrict__ K) {
    size_t c = (size_t)blockIdx.x * 256 + threadIdx.x;   // chunk id
    int t      = (int)(c >> 11);           // 2048 chunks per tile
    int within = (int)(c & 2047);
    int row = within >> 4, cc = within & 15;
    int gn = t * NTILE + row;

    uint4 out = make_uint4(0u, 0u, 0u, 0u);
    if (gn < NKEYS) {
        const float4* K4 = (const float4*)K;
        float4 v0 = K4[(size_t)gn * 32 + cc * 2];
        float4 v1 = K4[(size_t)gn * 32 + cc * 2 + 1];
        asm("cvt.rn.satfinite.bf16x2.f32 %0, %1, %2;" : "=r"(out.x) : "f"(v0.y), "f"(v0.x));
        asm("cvt.rn.satfinite.bf16x2.f32 %0, %1, %2;" : "=r"(out.y) : "f"(v0.w), "f"(v0.z));
        asm("cvt.rn.satfinite.bf16x2.f32 %0, %1, %2;" : "=r"(out.z) : "f"(v1.y), "f"(v1.x));
        asm("cvt.rn.satfinite.bf16x2.f32 %0, %1, %2;" : "=r"(out.w) : "f"(v1.w), "f"(v1.z));
    }
    char* kb = (char*)g_kb4;
    *(uint4*)(kb + (size_t)t * TILE_B + sw_off(row, cc)) = out;
}

// ---------------------------------------------------------------------------
// Kernel 1: persistent bf16 GEMM, bulk-copy double-buffered K + register top-k
// ---------------------------------------------------------------------------
__global__ __launch_bounds__(THREADS, 2) void gemm_topk(const float* __restrict__ Q) {
    extern __shared__ char sm[];
    const uint32_t smb = smem_u32(sm);

    const int tid  = threadIdx.x;
    const int lane = tid & 31;
    const int wid  = tid >> 5;
    const int wm   = wid >> 1;          // 0..3 (M)
    const int wn   = wid & 1;           // 0..1 (N)

    const int cta = blockIdx.x;
    const int h   = (cta < HALF_CTAS) ? 0 : 1;            // query half
    const int cl  = (h == 0) ? cta : (cta - HALF_CTAS);   // 0..147

    if (tid == 0) {
        MBAR_INIT(smb + SM_MBAR, 1);
        MBAR_INIT(smb + SM_MBAR + 8, 1);
    }

    // ---- stage Q half as bf16 (swizzled) ----
    const float4* Q4 = (const float4*)Q;
    #pragma unroll
    for (int i = 0; i < 16; ++i) {
        int v = tid + i * 256;
        int r = v >> 5, f = v & 31;
        cvt_store(sm, SM_Q, r, f, Q4[(size_t)(h * 128 + r) * 32 + f]);
    }
    __syncthreads();

    const char* kb = (const char*)g_kb4;
    auto issue = [&](int t, int buf) {
        if (tid == 0) {
            uint32_t mb = smb + SM_MBAR + buf * 8;
            MBAR_EXPECT(mb, TILE_B);
            BULK_G2S(smb + SM_K0 + buf * TILE_B, kb + (size_t)t * TILE_B, TILE_B, mb);
        }
    };

    // ldmatrix lane address components
    const int a_r = (lane & 15);
    const int a_c = (lane >> 4);
    const int b_r = (lane & 7) + ((lane >> 4) << 3);
    const int b_c = (lane >> 3) & 1;
    const int g   = lane >> 2;          // row group 0..7
    const int tq  = lane & 3;

    // per-thread top-3 for each of 4 owned rows (mt,hi)
    float ts[4][TPK];
    int   ti[4][TPK];
    #pragma unroll
    for (int l = 0; l < 4; ++l)
        #pragma unroll
        for (int j = 0; j < TPK; ++j) { ts[l][j] = -CUDART_INF_F; ti[l][j] = 0; }

    // prologue: fill both buffers
    issue(cl, 0);
    if (cl + HALF_CTAS < NTILES) issue(cl + HALF_CTAS, 1);

    uint32_t par[2] = {0, 0};
    int j = 0;
    for (int t = cl; t < NTILES; t += HALF_CTAS, ++j) {
        const int n_base = t * NTILE;
        const int buf = j & 1;

        mbar_wait(smb + SM_MBAR + buf * 8, par[buf]);
        par[buf] ^= 1;

        const uint32_t kbase = smb + SM_K0 + buf * TILE_B;

        // ---- MMA: warp tile 32(M) x 64(N) ----
        float acc[2][8][4];
        #pragma unroll
        for (int mt = 0; mt < 2; ++mt)
            #pragma unroll
            for (int nt = 0; nt < 8; ++nt)
                #pragma unroll
                for (int e = 0; e < 4; ++e)
                    acc[mt][nt][e] = 0.f;

        #pragma unroll
        for (int ks = 0; ks < 8; ++ks) {
            uint32_t a[2][4];
            #pragma unroll
            for (int mt = 0; mt < 2; ++mt) {
                uint32_t off = sw_off(wm * 32 + mt * 16 + a_r, ks * 2 + a_c);
                ldsm4(a[mt][0], a[mt][1], a[mt][2], a[mt][3], smb + SM_Q + off);
            }
            uint32_t b[16];
            #pragma unroll
            for (int p = 0; p < 4; ++p) {
                uint32_t off = sw_off(wn * 64 + p * 16 + b_r, ks * 2 + b_c);
                ldsm4(b[p*4+0], b[p*4+1], b[p*4+2], b[p*4+3], kbase + off);
            }
            #pragma unroll
            for (int mt = 0; mt < 2; ++mt)
                #pragma unroll
                for (int nt = 0; nt < 8; ++nt)
                    mma_bf16(acc[mt][nt], a[mt], b[nt*2], b[nt*2+1]);
        }

        // ---- scan accumulators in registers ----
        if (n_base + NTILE <= NKEYS) {
            #pragma unroll
            for (int mt = 0; mt < 2; ++mt)
                #pragma unroll
                for (int hi = 0; hi < 2; ++hi) {
                    float* lts = ts[mt * 2 + hi];
                    int*   lti = ti[mt * 2 + hi];
                    #pragma unroll
                    for (int nt = 0; nt < 8; ++nt) {
                        int n0 = n_base + wn * 64 + nt * 8 + tq * 2;
                        insT(lts, lti, acc[mt][nt][hi * 2 + 0], n0);
                        insT(lts, lti, acc[mt][nt][hi * 2 + 1], n0 + 1);
                    }
                }
        } else {
            #pragma unroll
            for (int mt = 0; mt < 2; ++mt)
                #pragma unroll
                for (int hi = 0; hi < 2; ++hi) {
                    float* lts = ts[mt * 2 + hi];
                    int*   lti = ti[mt * 2 + hi];
                    #pragma unroll
                    for (int nt = 0; nt < 8; ++nt) {
                        int n0 = n_base + wn * 64 + nt * 8 + tq * 2;
                        if (n0     < NKEYS) insT(lts, lti, acc[mt][nt][hi * 2 + 0], n0);
                        if (n0 + 1 < NKEYS) insT(lts, lti, acc[mt][nt][hi * 2 + 1], n0 + 1);
                    }
                }
        }

        __syncthreads();   // everyone done reading buf
        int t2 = t + 2 * HALF_CTAS;
        if (t2 < NTILES) issue(t2, buf);
    }

    // ---- CTA merge: 24 candidates per row -> top-8 per row ----
    __syncthreads();
    float* cs = (float*)sm;
    int*   ci = (int*)(sm + 128 * 24 * 4);
    #pragma unroll
    for (int mt = 0; mt < 2; ++mt)
        #pragma unroll
        for (int hi = 0; hi < 2; ++hi) {
            int row = wm * 32 + mt * 16 + hi * 8 + g;
            int slot = (wn * 4 + tq) * TPK;
            #pragma unroll
            for (int j2 = 0; j2 < TPK; ++j2) {
                cs[row * 24 + slot + j2] = ts[mt * 2 + hi][j2];
                ci[row * 24 + slot + j2] = ti[mt * 2 + hi][j2];
            }
        }
    __syncthreads();

    if (tid < 128) {
        float fs[TOPK];
        int   fi[TOPK];
        #pragma unroll
        for (int j2 = 0; j2 < TOPK; ++j2) { fs[j2] = -CUDART_INF_F; fi[j2] = 0; }
        #pragma unroll
        for (int e = 0; e < 24; ++e)
            ins8(fs, fi, cs[tid * 24 + e], ci[tid * 24 + e]);
        int q = h * 128 + tid;
        #pragma unroll
        for (int j2 = 0; j2 < TOPK; ++j2) {
            g_cand_s[((size_t)q * HALF_CTAS + cl) * TOPK + j2] = fs[j2];
            g_cand_i[((size_t)q * HALF_CTAS + cl) * TOPK + j2] = fi[j2];
        }
    }
}

// ---------------------------------------------------------------------------
// Kernel 2: approx-merge 1184 -> margin set -> exact fp32 rescore -> top-8 +
// slot gather.  One block per query, 256 threads.
// ---------------------------------------------------------------------------
#define MT 256
#define LCAP 64
__global__ __launch_bounds__(MT) void topk_rescore_gather(const float* __restrict__ Q,
                                                          const float* __restrict__ K,
                                                          const float* __restrict__ slots,
                                                          float* __restrict__ out_slots,
                                                          float* __restrict__ out_scores) {
    const int b    = blockIdx.x;
    const int tid  = threadIdx.x;
    const int lane = tid & 31;
    const int wrp  = tid >> 5;

    __shared__ float qrow[DIM];
    if (tid < DIM) qrow[tid] = Q[(size_t)b * DIM + tid];

    float ts[TOPK];
    int   ti[TOPK];
    #pragma unroll
    for (int j = 0; j < TOPK; ++j) { ts[j] = -CUDART_INF_F; ti[j] = 0; }
    for (int i = tid; i < NC_PER_Q; i += MT)
        ins8(ts, ti, g_cand_s[(size_t)b * NC_PER_Q + i], g_cand_i[(size_t)b * NC_PER_Q + i]);

    __shared__ float sscore[MT * TOPK];
    #pragma unroll
    for (int j = 0; j < TOPK; ++j)
        sscore[tid * TOPK + j] = ts[j];
    __syncthreads();

    __shared__ float rs[MT];
    __shared__ int   rp[MT];
    __shared__ float thresh;

    for (int r = 0; r < TOPK; ++r) {
        float best = -CUDART_INF_F;
        int   bpos = 0;
        #pragma unroll
        for (int j = 0; j < TOPK; ++j) {
            int p = tid + j * MT;
            float v = sscore[p];
            if (v > best) { best = v; bpos = p; }
        }
        rs[tid] = best;
        rp[tid] = bpos;
        __syncthreads();
        for (int st = MT / 2; st > 0; st >>= 1) {
            if (tid < st) {
                if (rs[tid + st] > rs[tid]) {
                    rs[tid] = rs[tid + st];
                    rp[tid] = rp[tid + st];
                }
            }
            __syncthreads();
        }
        if (tid == 0) {
            int p = rp[0];
            if (r == TOPK - 1) thresh = sscore[p] - 0.25f;
            sscore[p] = -CUDART_INF_F;
        }
        __syncthreads();
    }

    __shared__ int   lcnt;
    __shared__ int   li[LCAP];
    __shared__ float es[LCAP];
    if (tid == 0) lcnt = 0;
    __syncthreads();
    float tau = thresh;
    for (int i = tid; i < NC_PER_Q; i += MT) {
        float s = g_cand_s[(size_t)b * NC_PER_Q + i];
        if (s >= tau) {
            int p = atomicAdd(&lcnt, 1);
            if (p < LCAP) li[p] = g_cand_i[(size_t)b * NC_PER_Q + i];
        }
    }
    __syncthreads();
    int n = lcnt < LCAP ? lcnt : LCAP;

    const float4* K4 = (const float4*)K;
    for (int c = wrp; c < n; c += 8) {
        float4 kv = K4[(size_t)li[c] * 32 + lane];
        float4 qv = *(const float4*)&qrow[lane * 4];
        float d = kv.x * qv.x + kv.y * qv.y + kv.z * qv.z + kv.w * qv.w;
        #pragma unroll
        for (int o = 16; o; o >>= 1) d += __shfl_xor_sync(0xFFFFFFFFu, d, o);
        if (lane == 0) es[c] = d;
    }
    __syncthreads();

    __shared__ float wsc[TOPK];
    __shared__ int   widx[TOPK];
    if (tid == 0) {
        float fs[TOPK];
        int   fi[TOPK];
        #pragma unroll
        for (int j = 0; j < TOPK; ++j) { fs[j] = -CUDART_INF_F; fi[j] = 0; }
        for (int c = 0; c < n; ++c)
            ins8(fs, fi, es[c], li[c]);
        #pragma unroll
        for (int j = 0; j < TOPK; ++j) { wsc[j] = fs[j]; widx[j] = fi[j]; }
    }
    __syncthreads();

    if (tid < TOPK)
        out_scores[b * TOPK + tid] = wsc[tid];

    #pragma unroll
    for (int j = 0; j < TOPK; ++j)
        out_slots[((size_t)b * TOPK + j) * SLOT + tid] =
            slots[(size_t)widx[j] * SLOT + tid];
}

// ---------------------------------------------------------------------------
extern "C" void kernel_launch(void* const* d_in, const int* in_sizes, int n_in,
                              void* d_out, int out_size) {
    const float* Q = (const float*)d_in[0];
    const float* K = (const float*)d_in[1];
    const float* S = (const float*)d_in[2];

    float* out        = (float*)d_out;
    float* out_slots  = out;                              // [256, 8, 256]
    float* out_scores = out + (size_t)BQ * TOPK * SLOT;   // [256, 8]

    convert_k<<<NTILES * 8, 256>>>(K);                    // 12504 blocks

    cudaFuncSetAttribute(gemm_topk, cudaFuncAttributeMaxDynamicSharedMemorySize, SM_TOTAL);
    gemm_topk<<<NCTA, THREADS, SM_TOTAL>>>(Q);
    topk_rescore_gather<<<BQ, MT>>>(Q, K, S, out_slots, out_scores);
}